// round 4
// baseline (speedup 1.0000x reference)
#include <cuda_runtime.h>
#include <cuda_bf16.h>

#define N_NODES 40000
#define N_EDGES 640000
#define HIDDEN  128
#define N_GRAPHS 256
#define N_CLASSES 5

// ---------------- scratch (static device globals; no runtime alloc) ----------
__device__ float g_y[N_NODES * HIDDEN];     // dinv-scaled GEMM output (gather source)
__device__ float g_h[N_NODES * HIDDEN];     // aggregated / activated features
__device__ float g_dinv[N_NODES];
__device__ int   g_deg[N_NODES];
__device__ int   g_rowptr[N_NODES + 1];
__device__ int   g_cursor[N_NODES];
__device__ int   g_csrc[N_EDGES];
__device__ float g_s[N_GRAPHS * HIDDEN];    // pooled means
__device__ float g_WC[HIDDEN * N_CLASSES];  // W3 @ Wl
__device__ float g_bc[N_CLASSES];           // b3 @ Wl + bl

// ---------------- CSR build ---------------------------------------------------
__global__ void init_deg_kernel() {
    int i = blockIdx.x * blockDim.x + threadIdx.x;
    if (i < N_NODES) g_deg[i] = 0;
}

__global__ void count_deg_kernel(const int* __restrict__ ei) {
    int e = blockIdx.x * blockDim.x + threadIdx.x;
    if (e < N_EDGES) atomicAdd(&g_deg[ei[N_EDGES + e]], 1);  // dst row
}

// single-block exclusive scan over 40000 ints; also writes cursor + dinv
__global__ void scan_kernel() {
    const int NT = 1024;
    int tid = threadIdx.x;
    int lane = tid & 31, wid = tid >> 5;
    __shared__ int wsum[32];
    __shared__ int s_carry;
    if (tid == 0) s_carry = 0;
    __syncthreads();
    for (int base = 0; base < N_NODES; base += NT) {
        int i = base + tid;
        int v = (i < N_NODES) ? g_deg[i] : 0;
        int x = v;
        #pragma unroll
        for (int d = 1; d < 32; d <<= 1) {
            int t = __shfl_up_sync(0xffffffffu, x, d);
            if (lane >= d) x += t;
        }
        if (lane == 31) wsum[wid] = x;
        __syncthreads();
        if (wid == 0) {
            int w = wsum[lane];
            #pragma unroll
            for (int d = 1; d < 32; d <<= 1) {
                int t = __shfl_up_sync(0xffffffffu, w, d);
                if (lane >= d) w += t;
            }
            wsum[lane] = w;
        }
        __syncthreads();
        int carry = s_carry;
        int woff = (wid == 0) ? 0 : wsum[wid - 1];
        int incl = x + woff + carry;
        int excl = incl - v;
        if (i < N_NODES) {
            g_rowptr[i] = excl;
            g_cursor[i] = excl;
            g_dinv[i]   = rsqrtf((float)(v + 1));  // +1 self loop
        }
        __syncthreads();
        if (tid == NT - 1) s_carry = incl;
        __syncthreads();
    }
    if (tid == 0) g_rowptr[N_NODES] = s_carry;
}

__global__ void fill_csr_kernel(const int* __restrict__ ei) {
    int e = blockIdx.x * blockDim.x + threadIdx.x;
    if (e < N_EDGES) {
        int dst = ei[N_EDGES + e];
        int src = ei[e];
        int p = atomicAdd(&g_cursor[dst], 1);
        g_csrc[p] = src;
    }
}

// ---------------- GEMM: Y[i,:] = dinv[i] * (A[i,:] @ W) -----------------------
// A: [N_NODES,128], W: [128,128]. 256 threads, BM=128, 8x8 microtile, BK=32.
__global__ __launch_bounds__(256) void gemm_dinv_kernel(
    const float* __restrict__ A, const float* __restrict__ W, float* __restrict__ Y)
{
    __shared__ __align__(16) float As[32 * 132];  // [k][row], padded row-dim stride 132
    __shared__ __align__(16) float Bs[32 * 128];  // [k][col]

    int tid = threadIdx.x;
    int tx = tid & 15;        // col group
    int ty = tid >> 4;        // row group
    int row0 = blockIdx.x * 128;

    float acc[8][8];
    #pragma unroll
    for (int i = 0; i < 8; i++)
        #pragma unroll
        for (int j = 0; j < 8; j++) acc[i][j] = 0.f;

    for (int k0 = 0; k0 < 128; k0 += 32) {
        // load A chunk (128 rows x 32 k) transposed into As[k][row]
        #pragma unroll
        for (int j = 0; j < 4; j++) {
            int f = tid + 256 * j;          // 0..1023
            int r = f >> 3;                 // 0..127
            int kk = (f & 7) * 4;           // 0..28
            float4 v = make_float4(0.f, 0.f, 0.f, 0.f);
            int gr = row0 + r;
            if (gr < N_NODES)
                v = *reinterpret_cast<const float4*>(&A[gr * 128 + k0 + kk]);
            As[(kk + 0) * 132 + r] = v.x;
            As[(kk + 1) * 132 + r] = v.y;
            As[(kk + 2) * 132 + r] = v.z;
            As[(kk + 3) * 132 + r] = v.w;
        }
        // load B chunk (32 k x 128 cols)
        #pragma unroll
        for (int j = 0; j < 4; j++) {
            int f = tid + 256 * j;          // 0..1023
            int r = f >> 5;                 // 0..31
            int c = (f & 31) * 4;           // 0..124
            float4 v = *reinterpret_cast<const float4*>(&W[(k0 + r) * 128 + c]);
            *reinterpret_cast<float4*>(&Bs[r * 128 + c]) = v;
        }
        __syncthreads();

        #pragma unroll
        for (int k = 0; k < 32; k++) {
            float4 a0 = *reinterpret_cast<const float4*>(&As[k * 132 + ty * 8]);
            float4 a1 = *reinterpret_cast<const float4*>(&As[k * 132 + ty * 8 + 4]);
            float4 b0 = *reinterpret_cast<const float4*>(&Bs[k * 128 + tx * 8]);
            float4 b1 = *reinterpret_cast<const float4*>(&Bs[k * 128 + tx * 8 + 4]);
            float a[8] = {a0.x, a0.y, a0.z, a0.w, a1.x, a1.y, a1.z, a1.w};
            float b[8] = {b0.x, b0.y, b0.z, b0.w, b1.x, b1.y, b1.z, b1.w};
            #pragma unroll
            for (int i = 0; i < 8; i++)
                #pragma unroll
                for (int j = 0; j < 8; j++) acc[i][j] = fmaf(a[i], b[j], acc[i][j]);
        }
        __syncthreads();
    }

    #pragma unroll
    for (int i = 0; i < 8; i++) {
        int r = row0 + ty * 8 + i;
        if (r < N_NODES) {
            float d = g_dinv[r];
            float4 o0 = make_float4(d * acc[i][0], d * acc[i][1], d * acc[i][2], d * acc[i][3]);
            float4 o1 = make_float4(d * acc[i][4], d * acc[i][5], d * acc[i][6], d * acc[i][7]);
            *reinterpret_cast<float4*>(&Y[r * 128 + tx * 8])     = o0;
            *reinterpret_cast<float4*>(&Y[r * 128 + tx * 8 + 4]) = o1;
        }
    }
}

// ---------------- Aggregation: out[i] = act(dinv[i]*(y[i]+sum y[src]) + b) ----
// one warp per node; each lane owns a float4 feature chunk.
__global__ __launch_bounds__(256) void agg_kernel(
    const float* __restrict__ y, float* __restrict__ out,
    const float* __restrict__ bias, int do_relu)
{
    int warp = (blockIdx.x * blockDim.x + threadIdx.x) >> 5;
    int lane = threadIdx.x & 31;
    if (warp >= N_NODES) return;

    const float4* y4 = reinterpret_cast<const float4*>(y);
    float4 acc = y4[warp * 32 + lane];     // self-loop contribution
    int beg = g_rowptr[warp];
    int end = g_rowptr[warp + 1];

    int e = beg;
    // 2-deep pipelined edge loop
    int s_next = (e < end) ? __ldg(&g_csrc[e]) : 0;
    for (; e < end; e++) {
        int s = s_next;
        if (e + 1 < end) s_next = __ldg(&g_csrc[e + 1]);
        float4 v = y4[s * 32 + lane];
        acc.x += v.x; acc.y += v.y; acc.z += v.z; acc.w += v.w;
    }

    float d = g_dinv[warp];
    float4 b = bias ? reinterpret_cast<const float4*>(bias)[lane]
                    : make_float4(0.f, 0.f, 0.f, 0.f);
    float4 r;
    r.x = fmaf(d, acc.x, b.x);
    r.y = fmaf(d, acc.y, b.y);
    r.z = fmaf(d, acc.z, b.z);
    r.w = fmaf(d, acc.w, b.w);
    if (do_relu) {
        r.x = fmaxf(r.x, 0.f); r.y = fmaxf(r.y, 0.f);
        r.z = fmaxf(r.z, 0.f); r.w = fmaxf(r.w, 0.f);
    }
    reinterpret_cast<float4*>(out)[warp * 32 + lane] = r;
}

// ---------------- y = dinv * h (elementwise, for reassociated layer 3) --------
__global__ void scale_kernel(const float* __restrict__ h, float* __restrict__ y) {
    int i = blockIdx.x * blockDim.x + threadIdx.x;  // float4 index
    if (i < N_NODES * 32) {
        float d = g_dinv[i >> 5];
        float4 v = reinterpret_cast<const float4*>(h)[i];
        v.x *= d; v.y *= d; v.z *= d; v.w *= d;
        reinterpret_cast<float4*>(y)[i] = v;
    }
}

// ---------------- mean pool over sorted batch ---------------------------------
__global__ __launch_bounds__(128) void pool_kernel(const int* __restrict__ batch,
                                                   const float* __restrict__ h)
{
    int g = blockIdx.x;          // graph id
    __shared__ int s_beg, s_end;
    if (threadIdx.x == 0) {
        int lo = 0, hi = N_NODES;
        while (lo < hi) { int m = (lo + hi) >> 1; if (batch[m] < g) lo = m + 1; else hi = m; }
        s_beg = lo;
        lo = 0; hi = N_NODES;
        while (lo < hi) { int m = (lo + hi) >> 1; if (batch[m] < g + 1) lo = m + 1; else hi = m; }
        s_end = lo;
    }
    __syncthreads();
    int f = threadIdx.x;
    float sum = 0.f;
    for (int n = s_beg; n < s_end; n++) sum += h[n * 128 + f];
    float cnt = (float)(s_end - s_beg);
    g_s[g * 128 + f] = sum / fmaxf(cnt, 1.0f);
}

// ---------------- head fold: WC = W3@Wl, bc = b3@Wl + bl ----------------------
__global__ void head_fold_kernel(const float* __restrict__ W3, const float* __restrict__ b3,
                                 const float* __restrict__ Wl, const float* __restrict__ bl)
{
    int t = threadIdx.x;
    if (t < HIDDEN * N_CLASSES) {
        int j = t / N_CLASSES, c = t % N_CLASSES;
        float s = 0.f;
        for (int k = 0; k < HIDDEN; k++) s = fmaf(W3[j * HIDDEN + k], Wl[k * N_CLASSES + c], s);
        g_WC[t] = s;
    } else if (t < HIDDEN * N_CLASSES + N_CLASSES) {
        int c = t - HIDDEN * N_CLASSES;
        float s = bl[c];
        for (int k = 0; k < HIDDEN; k++) s = fmaf(b3[k], Wl[k * N_CLASSES + c], s);
        g_bc[c] = s;
    }
}

// ---------------- out[g,c] = s[g,:] @ WC[:,c] + bc[c] -------------------------
__global__ void out_kernel(float* __restrict__ out) {
    int t = blockIdx.x * blockDim.x + threadIdx.x;
    if (t < N_GRAPHS * N_CLASSES) {
        int g = t / N_CLASSES, c = t % N_CLASSES;
        float s = g_bc[c];
        for (int k = 0; k < HIDDEN; k++) s = fmaf(g_s[g * 128 + k], g_WC[k * N_CLASSES + c], s);
        out[t] = s;
    }
}

// ---------------- launcher ----------------------------------------------------
extern "C" void kernel_launch(void* const* d_in, const int* in_sizes, int n_in,
                              void* d_out, int out_size)
{
    const float* x     = (const float*)d_in[0];
    const int*   ei    = (const int*)  d_in[1];
    const int*   batch = (const int*)  d_in[2];
    const float* W1    = (const float*)d_in[3];
    const float* b1    = (const float*)d_in[4];
    const float* W2    = (const float*)d_in[5];
    const float* b2    = (const float*)d_in[6];
    const float* W3    = (const float*)d_in[7];
    const float* b3    = (const float*)d_in[8];
    const float* Wl    = (const float*)d_in[9];
    const float* bl    = (const float*)d_in[10];
    float* out = (float*)d_out;

    float *yb, *hb;
    cudaGetSymbolAddress((void**)&yb, g_y);
    cudaGetSymbolAddress((void**)&hb, g_h);

    const int EB = (N_EDGES + 255) / 256;
    const int GEMM_BLOCKS = (N_NODES + 127) / 128;
    const int AGG_BLOCKS  = (N_NODES + 7) / 8;      // 8 warps per 256-thread block
    const int SC_BLOCKS   = (N_NODES * 32 + 255) / 256;

    // CSR build (per call; deterministic up to within-bucket order)
    init_deg_kernel<<<(N_NODES + 255) / 256, 256>>>();
    count_deg_kernel<<<EB, 256>>>(ei);
    scan_kernel<<<1, 1024>>>();
    fill_csr_kernel<<<EB, 256>>>(ei);

    // layer 1
    gemm_dinv_kernel<<<GEMM_BLOCKS, 256>>>(x, W1, yb);
    agg_kernel<<<AGG_BLOCKS, 256>>>(yb, hb, b1, 1);
    // layer 2
    gemm_dinv_kernel<<<GEMM_BLOCKS, 256>>>(hb, W2, yb);
    agg_kernel<<<AGG_BLOCKS, 256>>>(yb, hb, b2, 1);
    // layer 3 (reassociated: aggregate first, GEMM after pooling)
    scale_kernel<<<SC_BLOCKS, 256>>>(hb, yb);
    agg_kernel<<<AGG_BLOCKS, 256>>>(yb, hb, (const float*)nullptr, 0);

    // pool + folded head
    pool_kernel<<<N_GRAPHS, 128>>>(batch, hb);
    head_fold_kernel<<<1, HIDDEN * N_CLASSES + N_CLASSES>>>(W3, b3, Wl, bl);
    out_kernel<<<(N_GRAPHS * N_CLASSES + 255) / 256, 256>>>(out);
}

// round 5
// speedup vs baseline: 1.0400x; 1.0400x over previous
#include <cuda_runtime.h>
#include <cuda_bf16.h>

#define N_NODES 40000
#define N_EDGES 640000
#define HIDDEN  128
#define N_GRAPHS 256
#define N_CLASSES 5

// ---------------- scratch (static device globals; no runtime alloc) ----------
__device__ __align__(16) float g_y[N_NODES * HIDDEN];   // GEMM output / layer-3 agg result
__device__ __align__(16) float g_h[N_NODES * HIDDEN];   // aggregated / activated features
__device__ __align__(16) float g_dinv[N_NODES];
__device__ __align__(16) int   g_deg[N_NODES];
__device__ __align__(16) int   g_rowptr[N_NODES + 4];
__device__ __align__(16) int   g_cursor[N_NODES];
__device__ __align__(16) int   g_csrc[N_EDGES];
__device__ float g_s[N_GRAPHS * HIDDEN];    // pooled means
__device__ float g_WC[HIDDEN * N_CLASSES];  // W3 @ Wl
__device__ float g_bc[N_CLASSES];           // b3 @ Wl + bl

// ---------------- CSR build ---------------------------------------------------
// 4 edges per thread, int4 index loads, 4 independent atomic chains (MLP=4)
__global__ void count_deg_kernel(const int* __restrict__ ei) {
    int e4 = (blockIdx.x * blockDim.x + threadIdx.x) * 4;
    if (e4 < N_EDGES) {  // N_EDGES % 4 == 0, dst row is 16B-aligned
        int4 d = *reinterpret_cast<const int4*>(&ei[N_EDGES + e4]);
        atomicAdd(&g_deg[d.x], 1);
        atomicAdd(&g_deg[d.y], 1);
        atomicAdd(&g_deg[d.z], 1);
        atomicAdd(&g_deg[d.w], 1);
    }
}

// single-block exclusive scan over 40000 ints, 4 elements/thread (10 iterations)
__global__ void scan_kernel() {
    const int NT = 1024;
    int tid = threadIdx.x;
    int lane = tid & 31, wid = tid >> 5;
    __shared__ int wsum[32];
    __shared__ int s_carry;
    if (tid == 0) s_carry = 0;
    __syncthreads();
    for (int base = 0; base < N_NODES; base += NT * 4) {
        int i4 = base + tid * 4;
        int4 v = make_int4(0, 0, 0, 0);
        if (i4 < N_NODES)  // tail block is a whole multiple of 4, full int4 ok
            v = *reinterpret_cast<const int4*>(&g_deg[i4]);
        int s = v.x + v.y + v.z + v.w;
        int x = s;
        #pragma unroll
        for (int d = 1; d < 32; d <<= 1) {
            int t = __shfl_up_sync(0xffffffffu, x, d);
            if (lane >= d) x += t;
        }
        if (lane == 31) wsum[wid] = x;
        __syncthreads();
        if (wid == 0) {
            int w = wsum[lane];
            #pragma unroll
            for (int d = 1; d < 32; d <<= 1) {
                int t = __shfl_up_sync(0xffffffffu, w, d);
                if (lane >= d) w += t;
            }
            wsum[lane] = w;
        }
        __syncthreads();
        int carry = s_carry;
        int woff = (wid == 0) ? 0 : wsum[wid - 1];
        int incl = x + woff + carry;       // inclusive over 4-element groups
        int e0 = incl - s;                 // exclusive start of this thread's 4
        if (i4 < N_NODES) {
            int4 rp = make_int4(e0, e0 + v.x, e0 + v.x + v.y, e0 + v.x + v.y + v.z);
            *reinterpret_cast<int4*>(&g_rowptr[i4]) = rp;
            *reinterpret_cast<int4*>(&g_cursor[i4]) = rp;
            float4 dv = make_float4(rsqrtf((float)(v.x + 1)), rsqrtf((float)(v.y + 1)),
                                    rsqrtf((float)(v.z + 1)), rsqrtf((float)(v.w + 1)));
            *reinterpret_cast<float4*>(&g_dinv[i4]) = dv;
        }
        __syncthreads();
        if (tid == NT - 1) s_carry = incl;
        __syncthreads();
    }
    if (tid == 0) g_rowptr[N_NODES] = s_carry;
}

__global__ void fill_csr_kernel(const int* __restrict__ ei) {
    int e4 = (blockIdx.x * blockDim.x + threadIdx.x) * 4;
    if (e4 < N_EDGES) {
        int4 s = *reinterpret_cast<const int4*>(&ei[e4]);
        int4 d = *reinterpret_cast<const int4*>(&ei[N_EDGES + e4]);
        int p0 = atomicAdd(&g_cursor[d.x], 1);
        int p1 = atomicAdd(&g_cursor[d.y], 1);
        int p2 = atomicAdd(&g_cursor[d.z], 1);
        int p3 = atomicAdd(&g_cursor[d.w], 1);
        g_csrc[p0] = s.x;
        g_csrc[p1] = s.y;
        g_csrc[p2] = s.z;
        g_csrc[p3] = s.w;
    }
}

// ---------------- GEMM: Y[i,:] = dinv[i] * (A[i,:] @ W) -----------------------
__global__ __launch_bounds__(256) void gemm_dinv_kernel(
    const float* __restrict__ A, const float* __restrict__ W, float* __restrict__ Y)
{
    __shared__ __align__(16) float As[32 * 132];  // [k][row], padded
    __shared__ __align__(16) float Bs[32 * 128];  // [k][col]

    int tid = threadIdx.x;
    int tx = tid & 15;
    int ty = tid >> 4;
    int row0 = blockIdx.x * 128;

    float acc[8][8];
    #pragma unroll
    for (int i = 0; i < 8; i++)
        #pragma unroll
        for (int j = 0; j < 8; j++) acc[i][j] = 0.f;

    for (int k0 = 0; k0 < 128; k0 += 32) {
        #pragma unroll
        for (int j = 0; j < 4; j++) {
            int f = tid + 256 * j;
            int r = f >> 3;
            int kk = (f & 7) * 4;
            float4 v = make_float4(0.f, 0.f, 0.f, 0.f);
            int gr = row0 + r;
            if (gr < N_NODES)
                v = *reinterpret_cast<const float4*>(&A[gr * 128 + k0 + kk]);
            As[(kk + 0) * 132 + r] = v.x;
            As[(kk + 1) * 132 + r] = v.y;
            As[(kk + 2) * 132 + r] = v.z;
            As[(kk + 3) * 132 + r] = v.w;
        }
        #pragma unroll
        for (int j = 0; j < 4; j++) {
            int f = tid + 256 * j;
            int r = f >> 5;
            int c = (f & 31) * 4;
            float4 v = *reinterpret_cast<const float4*>(&W[(k0 + r) * 128 + c]);
            *reinterpret_cast<float4*>(&Bs[r * 128 + c]) = v;
        }
        __syncthreads();

        #pragma unroll
        for (int k = 0; k < 32; k++) {
            float4 a0 = *reinterpret_cast<const float4*>(&As[k * 132 + ty * 8]);
            float4 a1 = *reinterpret_cast<const float4*>(&As[k * 132 + ty * 8 + 4]);
            float4 b0 = *reinterpret_cast<const float4*>(&Bs[k * 128 + tx * 8]);
            float4 b1 = *reinterpret_cast<const float4*>(&Bs[k * 128 + tx * 8 + 4]);
            float a[8] = {a0.x, a0.y, a0.z, a0.w, a1.x, a1.y, a1.z, a1.w};
            float b[8] = {b0.x, b0.y, b0.z, b0.w, b1.x, b1.y, b1.z, b1.w};
            #pragma unroll
            for (int i = 0; i < 8; i++)
                #pragma unroll
                for (int j = 0; j < 8; j++) acc[i][j] = fmaf(a[i], b[j], acc[i][j]);
        }
        __syncthreads();
    }

    #pragma unroll
    for (int i = 0; i < 8; i++) {
        int r = row0 + ty * 8 + i;
        if (r < N_NODES) {
            float d = g_dinv[r];
            float4 o0 = make_float4(d * acc[i][0], d * acc[i][1], d * acc[i][2], d * acc[i][3]);
            float4 o1 = make_float4(d * acc[i][4], d * acc[i][5], d * acc[i][6], d * acc[i][7]);
            *reinterpret_cast<float4*>(&Y[r * 128 + tx * 8])     = o0;
            *reinterpret_cast<float4*>(&Y[r * 128 + tx * 8 + 4]) = o1;
        }
    }
}

// ---------------- Aggregation -------------------------------------------------
// out[i] = act( dinv[i] * ( w(i)*y[i] + sum_{src} w(src)*y[src] ) + b )
// w(s) = dinv[s] if scale_src else 1.  One warp per node, float4 per lane.
// Edge loop unrolled x4 with prefetched indices (MLP=4) and dual accumulators.
__global__ __launch_bounds__(256) void agg_kernel(
    const float* __restrict__ y, float* __restrict__ out,
    const float* __restrict__ bias, int do_relu, int scale_src)
{
    int warp = (blockIdx.x * blockDim.x + threadIdx.x) >> 5;
    int lane = threadIdx.x & 31;
    if (warp >= N_NODES) return;

    const float4* y4 = reinterpret_cast<const float4*>(y);
    float di = g_dinv[warp];
    float ws = scale_src ? di : 1.f;

    float4 self = y4[warp * 32 + lane];
    float4 acc0 = make_float4(ws * self.x, ws * self.y, ws * self.z, ws * self.w);
    float4 acc1 = make_float4(0.f, 0.f, 0.f, 0.f);

    int e   = g_rowptr[warp];
    int end = g_rowptr[warp + 1];

    for (; e + 4 <= end; e += 4) {
        int s0 = __ldg(&g_csrc[e]);
        int s1 = __ldg(&g_csrc[e + 1]);
        int s2 = __ldg(&g_csrc[e + 2]);
        int s3 = __ldg(&g_csrc[e + 3]);
        float w0 = scale_src ? __ldg(&g_dinv[s0]) : 1.f;
        float w1 = scale_src ? __ldg(&g_dinv[s1]) : 1.f;
        float w2 = scale_src ? __ldg(&g_dinv[s2]) : 1.f;
        float w3 = scale_src ? __ldg(&g_dinv[s3]) : 1.f;
        float4 v0 = y4[s0 * 32 + lane];
        float4 v1 = y4[s1 * 32 + lane];
        float4 v2 = y4[s2 * 32 + lane];
        float4 v3 = y4[s3 * 32 + lane];
        acc0.x = fmaf(w0, v0.x, acc0.x); acc0.y = fmaf(w0, v0.y, acc0.y);
        acc0.z = fmaf(w0, v0.z, acc0.z); acc0.w = fmaf(w0, v0.w, acc0.w);
        acc1.x = fmaf(w1, v1.x, acc1.x); acc1.y = fmaf(w1, v1.y, acc1.y);
        acc1.z = fmaf(w1, v1.z, acc1.z); acc1.w = fmaf(w1, v1.w, acc1.w);
        acc0.x = fmaf(w2, v2.x, acc0.x); acc0.y = fmaf(w2, v2.y, acc0.y);
        acc0.z = fmaf(w2, v2.z, acc0.z); acc0.w = fmaf(w2, v2.w, acc0.w);
        acc1.x = fmaf(w3, v3.x, acc1.x); acc1.y = fmaf(w3, v3.y, acc1.y);
        acc1.z = fmaf(w3, v3.z, acc1.z); acc1.w = fmaf(w3, v3.w, acc1.w);
    }
    for (; e < end; e++) {
        int s = __ldg(&g_csrc[e]);
        float w = scale_src ? __ldg(&g_dinv[s]) : 1.f;
        float4 v = y4[s * 32 + lane];
        acc0.x = fmaf(w, v.x, acc0.x); acc0.y = fmaf(w, v.y, acc0.y);
        acc0.z = fmaf(w, v.z, acc0.z); acc0.w = fmaf(w, v.w, acc0.w);
    }

    acc0.x += acc1.x; acc0.y += acc1.y; acc0.z += acc1.z; acc0.w += acc1.w;

    float4 b = bias ? reinterpret_cast<const float4*>(bias)[lane]
                    : make_float4(0.f, 0.f, 0.f, 0.f);
    float4 r;
    r.x = fmaf(di, acc0.x, b.x);
    r.y = fmaf(di, acc0.y, b.y);
    r.z = fmaf(di, acc0.z, b.z);
    r.w = fmaf(di, acc0.w, b.w);
    if (do_relu) {
        r.x = fmaxf(r.x, 0.f); r.y = fmaxf(r.y, 0.f);
        r.z = fmaxf(r.z, 0.f); r.w = fmaxf(r.w, 0.f);
    }
    reinterpret_cast<float4*>(out)[warp * 32 + lane] = r;
}

// ---------------- mean pool over sorted batch ---------------------------------
__global__ __launch_bounds__(128) void pool_kernel(const int* __restrict__ batch,
                                                   const float* __restrict__ h)
{
    int g = blockIdx.x;
    __shared__ int s_beg, s_end;
    if (threadIdx.x == 0) {
        int lo = 0, hi = N_NODES;
        while (lo < hi) { int m = (lo + hi) >> 1; if (batch[m] < g) lo = m + 1; else hi = m; }
        s_beg = lo;
        lo = 0; hi = N_NODES;
        while (lo < hi) { int m = (lo + hi) >> 1; if (batch[m] < g + 1) lo = m + 1; else hi = m; }
        s_end = lo;
    }
    __syncthreads();
    int f = threadIdx.x;
    float sum = 0.f;
    for (int n = s_beg; n < s_end; n++) sum += h[n * 128 + f];
    float cnt = (float)(s_end - s_beg);
    g_s[g * 128 + f] = sum / fmaxf(cnt, 1.0f);
}

// ---------------- head fold: WC = W3@Wl, bc = b3@Wl + bl ----------------------
__global__ void head_fold_kernel(const float* __restrict__ W3, const float* __restrict__ b3,
                                 const float* __restrict__ Wl, const float* __restrict__ bl)
{
    int t = threadIdx.x;
    if (t < HIDDEN * N_CLASSES) {
        int j = t / N_CLASSES, c = t % N_CLASSES;
        float s = 0.f;
        for (int k = 0; k < HIDDEN; k++) s = fmaf(W3[j * HIDDEN + k], Wl[k * N_CLASSES + c], s);
        g_WC[t] = s;
    } else if (t < HIDDEN * N_CLASSES + N_CLASSES) {
        int c = t - HIDDEN * N_CLASSES;
        float s = bl[c];
        for (int k = 0; k < HIDDEN; k++) s = fmaf(b3[k], Wl[k * N_CLASSES + c], s);
        g_bc[c] = s;
    }
}

// ---------------- out[g,c] = s[g,:] @ WC[:,c] + bc[c] -------------------------
__global__ void out_kernel(float* __restrict__ out) {
    int t = blockIdx.x * blockDim.x + threadIdx.x;
    if (t < N_GRAPHS * N_CLASSES) {
        int g = t / N_CLASSES, c = t % N_CLASSES;
        float s = g_bc[c];
        for (int k = 0; k < HIDDEN; k++) s = fmaf(g_s[g * 128 + k], g_WC[k * N_CLASSES + c], s);
        out[t] = s;
    }
}

// ---------------- launcher ----------------------------------------------------
extern "C" void kernel_launch(void* const* d_in, const int* in_sizes, int n_in,
                              void* d_out, int out_size)
{
    const float* x     = (const float*)d_in[0];
    const int*   ei    = (const int*)  d_in[1];
    const int*   batch = (const int*)  d_in[2];
    const float* W1    = (const float*)d_in[3];
    const float* b1    = (const float*)d_in[4];
    const float* W2    = (const float*)d_in[5];
    const float* b2    = (const float*)d_in[6];
    const float* W3    = (const float*)d_in[7];
    const float* b3    = (const float*)d_in[8];
    const float* Wl    = (const float*)d_in[9];
    const float* bl    = (const float*)d_in[10];
    float* out = (float*)d_out;

    float *yb, *hb;
    void* degPtr;
    cudaGetSymbolAddress((void**)&yb, g_y);
    cudaGetSymbolAddress((void**)&hb, g_h);
    cudaGetSymbolAddress(&degPtr, g_deg);

    const int EB4 = (N_EDGES / 4 + 255) / 256;       // 625 blocks, 4 edges/thread
    const int GEMM_BLOCKS = (N_NODES + 127) / 128;
    const int AGG_BLOCKS  = (N_NODES + 7) / 8;       // 8 warps per 256-thread block

    // CSR build
    cudaMemsetAsync(degPtr, 0, N_NODES * sizeof(int));
    count_deg_kernel<<<EB4, 256>>>(ei);
    scan_kernel<<<1, 1024>>>();
    fill_csr_kernel<<<EB4, 256>>>(ei);

    // layer 1
    gemm_dinv_kernel<<<GEMM_BLOCKS, 256>>>(x, W1, yb);
    agg_kernel<<<AGG_BLOCKS, 256>>>(yb, hb, b1, 1, 0);
    // layer 2
    gemm_dinv_kernel<<<GEMM_BLOCKS, 256>>>(hb, W2, yb);
    agg_kernel<<<AGG_BLOCKS, 256>>>(yb, hb, b2, 1, 0);
    // layer 3 (reassociated; dinv[src] scaling fused into the gather, hb -> yb)
    agg_kernel<<<AGG_BLOCKS, 256>>>(hb, yb, (const float*)nullptr, 0, 1);

    // pool + folded head
    pool_kernel<<<N_GRAPHS, 128>>>(batch, yb);
    head_fold_kernel<<<1, HIDDEN * N_CLASSES + N_CLASSES>>>(W3, b3, Wl, bl);
    out_kernel<<<(N_GRAPHS * N_CLASSES + 255) / 256, 256>>>(out);
}

// round 6
// speedup vs baseline: 1.1766x; 1.1314x over previous
#include <cuda_runtime.h>
#include <cuda_bf16.h>
#include <cstdint>

#define N_NODES 40000
#define N_EDGES 640000
#define HIDDEN  128
#define N_GRAPHS 256
#define N_CLASSES 5

// ---------------- scratch (static device globals; no runtime alloc) ----------
__device__ __align__(16) float g_y[N_NODES * HIDDEN];   // GEMM output / layer-3 agg result
__device__ __align__(16) float g_h[N_NODES * HIDDEN];   // aggregated / activated features
__device__ __align__(16) float g_dinv[N_NODES];
__device__ __align__(16) int   g_deg[N_NODES];
__device__ __align__(16) int   g_rowptr[N_NODES + 4];
__device__ __align__(16) int   g_cursor[N_NODES];
__device__ __align__(16) int   g_csrc[N_EDGES];
__device__ float g_s[N_GRAPHS * HIDDEN];    // pooled means
__device__ float g_WC[HIDDEN * N_CLASSES];  // W3 @ Wl
__device__ float g_bc[N_CLASSES];           // b3 @ Wl + bl
// Precomputed W fragments for tf32 MMA, per layer:
// [ (ks*16 + nt)*32 + lane ] -> float4 { b0_hi, b1_hi, b0_lo, b1_lo }
__device__ __align__(16) float g_wfrag[2][16 * 16 * 32 * 4];

// ---------------- tf32 helpers ------------------------------------------------
__device__ __forceinline__ unsigned f2tf32(float f) {
    unsigned u;
    asm("cvt.rna.tf32.f32 %0, %1;" : "=r"(u) : "f"(f));
    return u;
}

__device__ __forceinline__ void mma_tf32(float* d,
                                         unsigned a0, unsigned a1, unsigned a2, unsigned a3,
                                         unsigned b0, unsigned b1)
{
    asm volatile(
        "mma.sync.aligned.m16n8k8.row.col.f32.tf32.tf32.f32 "
        "{%0,%1,%2,%3}, {%4,%5,%6,%7}, {%8,%9}, {%0,%1,%2,%3};"
        : "+f"(d[0]), "+f"(d[1]), "+f"(d[2]), "+f"(d[3])
        : "r"(a0), "r"(a1), "r"(a2), "r"(a3), "r"(b0), "r"(b1));
}

// ---------------- CSR build ---------------------------------------------------
__global__ void count_deg_kernel(const int* __restrict__ ei) {
    int e4 = (blockIdx.x * blockDim.x + threadIdx.x) * 4;
    if (e4 < N_EDGES) {
        int4 d = *reinterpret_cast<const int4*>(&ei[N_EDGES + e4]);
        atomicAdd(&g_deg[d.x], 1);
        atomicAdd(&g_deg[d.y], 1);
        atomicAdd(&g_deg[d.z], 1);
        atomicAdd(&g_deg[d.w], 1);
    }
}

__global__ void scan_kernel() {
    const int NT = 1024;
    int tid = threadIdx.x;
    int lane = tid & 31, wid = tid >> 5;
    __shared__ int wsum[32];
    __shared__ int s_carry;
    if (tid == 0) s_carry = 0;
    __syncthreads();
    for (int base = 0; base < N_NODES; base += NT * 4) {
        int i4 = base + tid * 4;
        int4 v = make_int4(0, 0, 0, 0);
        if (i4 < N_NODES)
            v = *reinterpret_cast<const int4*>(&g_deg[i4]);
        int s = v.x + v.y + v.z + v.w;
        int x = s;
        #pragma unroll
        for (int d = 1; d < 32; d <<= 1) {
            int t = __shfl_up_sync(0xffffffffu, x, d);
            if (lane >= d) x += t;
        }
        if (lane == 31) wsum[wid] = x;
        __syncthreads();
        if (wid == 0) {
            int w = wsum[lane];
            #pragma unroll
            for (int d = 1; d < 32; d <<= 1) {
                int t = __shfl_up_sync(0xffffffffu, w, d);
                if (lane >= d) w += t;
            }
            wsum[lane] = w;
        }
        __syncthreads();
        int carry = s_carry;
        int woff = (wid == 0) ? 0 : wsum[wid - 1];
        int incl = x + woff + carry;
        int e0 = incl - s;
        if (i4 < N_NODES) {
            int4 rp = make_int4(e0, e0 + v.x, e0 + v.x + v.y, e0 + v.x + v.y + v.z);
            *reinterpret_cast<int4*>(&g_rowptr[i4]) = rp;
            *reinterpret_cast<int4*>(&g_cursor[i4]) = rp;
            float4 dv = make_float4(rsqrtf((float)(v.x + 1)), rsqrtf((float)(v.y + 1)),
                                    rsqrtf((float)(v.z + 1)), rsqrtf((float)(v.w + 1)));
            *reinterpret_cast<float4*>(&g_dinv[i4]) = dv;
        }
        __syncthreads();
        if (tid == NT - 1) s_carry = incl;
        __syncthreads();
    }
    if (tid == 0) g_rowptr[N_NODES] = s_carry;
}

__global__ void fill_csr_kernel(const int* __restrict__ ei) {
    int e4 = (blockIdx.x * blockDim.x + threadIdx.x) * 4;
    if (e4 < N_EDGES) {
        int4 s = *reinterpret_cast<const int4*>(&ei[e4]);
        int4 d = *reinterpret_cast<const int4*>(&ei[N_EDGES + e4]);
        int p0 = atomicAdd(&g_cursor[d.x], 1);
        int p1 = atomicAdd(&g_cursor[d.y], 1);
        int p2 = atomicAdd(&g_cursor[d.z], 1);
        int p3 = atomicAdd(&g_cursor[d.w], 1);
        g_csrc[p0] = s.x;
        g_csrc[p1] = s.y;
        g_csrc[p2] = s.z;
        g_csrc[p3] = s.w;
    }
}

// ---------------- W fragment precompute ---------------------------------------
// One thread per (layer, kstep, ntile, lane): packs {b0_hi, b1_hi, b0_lo, b1_lo}
// b0 = W[ks*8 + lane%4][nt*8 + lane/4], b1 = W[ks*8 + lane%4 + 4][nt*8 + lane/4]
__global__ void wfrag_kernel(const float* __restrict__ W1, const float* __restrict__ W2) {
    int t = blockIdx.x * blockDim.x + threadIdx.x;
    if (t >= 2 * 8192) return;
    int layer = t >> 13;
    int r = t & 8191;                 // (ks*16 + nt)*32 + lane
    int ks   = r >> 9;
    int lane = r & 31;
    int k0 = ks * 8 + (lane & 3);
    int n  = ((r >> 5) & 15) * 8 + (lane >> 2);
    const float* W = layer ? W2 : W1;
    float b0 = W[k0 * HIDDEN + n];
    float b1 = W[(k0 + 4) * HIDDEN + n];
    unsigned h0 = f2tf32(b0);
    unsigned h1 = f2tf32(b1);
    unsigned l0 = f2tf32(b0 - __uint_as_float(h0));
    unsigned l1 = f2tf32(b1 - __uint_as_float(h1));
    float4 o = make_float4(__uint_as_float(h0), __uint_as_float(h1),
                           __uint_as_float(l0), __uint_as_float(l1));
    *reinterpret_cast<float4*>(&g_wfrag[layer][r * 4]) = o;
}

// ---------------- GEMM (tf32 tensor cores, split precision) -------------------
// Y[i,:] = dinv[i] * (A[i,:] @ W)   via 3-term tf32 emulation (hi*hi+hi*lo+lo*hi)
// 256 threads = 8 warps; warp w handles rows [blk*128 + w*16, +16), full N=128.
__global__ __launch_bounds__(256) void gemm_tf32_kernel(
    const float* __restrict__ A, const float4* __restrict__ wfrag,
    float* __restrict__ Y)
{
    __shared__ __align__(16) float s_a[128 * 68];   // 128 rows x 64 k-cols, pad 4

    int tid  = threadIdx.x;
    int warp = tid >> 5;
    int lane = tid & 31;
    int row0 = blockIdx.x * 128;
    int wrow = row0 + warp * 16;

    float acc[64];
    #pragma unroll
    for (int i = 0; i < 64; i++) acc[i] = 0.f;

    const uint4* bf = reinterpret_cast<const uint4*>(wfrag);

    #pragma unroll
    for (int kh = 0; kh < 2; kh++) {
        // stage A half-tile: 128 rows x 64 cols, coalesced float4
        #pragma unroll
        for (int j = 0; j < 8; j++) {
            int idx = tid + 256 * j;            // 0..2047
            int r = idx >> 4;                   // 0..127
            int c = (idx & 15) * 4;             // 0..60
            int gr = row0 + r;
            float4 v = make_float4(0.f, 0.f, 0.f, 0.f);
            if (gr < N_NODES)
                v = *reinterpret_cast<const float4*>(&A[gr * 128 + kh * 64 + c]);
            *reinterpret_cast<float4*>(&s_a[r * 68 + c]) = v;
        }
        __syncthreads();

        #pragma unroll
        for (int ksl = 0; ksl < 8; ksl++) {
            int ks = kh * 8 + ksl;
            int c  = ksl * 8 + (lane & 3);
            int rA = warp * 16 + (lane >> 2);
            float f0 = s_a[rA * 68 + c];
            float f1 = s_a[(rA + 8) * 68 + c];
            float f2 = s_a[rA * 68 + c + 4];
            float f3 = s_a[(rA + 8) * 68 + c + 4];
            unsigned ah0 = f2tf32(f0), ah1 = f2tf32(f1), ah2 = f2tf32(f2), ah3 = f2tf32(f3);
            unsigned al0 = f2tf32(f0 - __uint_as_float(ah0));
            unsigned al1 = f2tf32(f1 - __uint_as_float(ah1));
            unsigned al2 = f2tf32(f2 - __uint_as_float(ah2));
            unsigned al3 = f2tf32(f3 - __uint_as_float(ah3));

            const uint4* bk = bf + ks * (16 * 32) + lane;
            #pragma unroll
            for (int nt = 0; nt < 16; nt++) {
                uint4 b = __ldg(bk + nt * 32);   // {b0_hi, b1_hi, b0_lo, b1_lo}
                float* d = acc + nt * 4;
                mma_tf32(d, ah0, ah1, ah2, ah3, b.x, b.y);  // hi*hi
                mma_tf32(d, ah0, ah1, ah2, ah3, b.z, b.w);  // hi*lo
                mma_tf32(d, al0, al1, al2, al3, b.x, b.y);  // lo*hi
            }
        }
        __syncthreads();
    }

    // epilogue: scale by dinv, store (float2 per fragment row)
    if (wrow < N_NODES) {
        int r0 = wrow + (lane >> 2);
        int r1 = r0 + 8;
        float d0 = g_dinv[r0];
        float d1 = g_dinv[r1];
        #pragma unroll
        for (int nt = 0; nt < 16; nt++) {
            int col = nt * 8 + (lane & 3) * 2;
            float2 o0 = make_float2(d0 * acc[nt * 4 + 0], d0 * acc[nt * 4 + 1]);
            float2 o1 = make_float2(d1 * acc[nt * 4 + 2], d1 * acc[nt * 4 + 3]);
            *reinterpret_cast<float2*>(&Y[r0 * 128 + col]) = o0;
            *reinterpret_cast<float2*>(&Y[r1 * 128 + col]) = o1;
        }
    }
}

// ---------------- Aggregation -------------------------------------------------
__global__ __launch_bounds__(256) void agg_kernel(
    const float* __restrict__ y, float* __restrict__ out,
    const float* __restrict__ bias, int do_relu, int scale_src)
{
    int warp = (blockIdx.x * blockDim.x + threadIdx.x) >> 5;
    int lane = threadIdx.x & 31;
    if (warp >= N_NODES) return;

    const float4* y4 = reinterpret_cast<const float4*>(y);
    float di = g_dinv[warp];
    float ws = scale_src ? di : 1.f;

    float4 self = y4[warp * 32 + lane];
    float4 acc0 = make_float4(ws * self.x, ws * self.y, ws * self.z, ws * self.w);
    float4 acc1 = make_float4(0.f, 0.f, 0.f, 0.f);

    int e   = g_rowptr[warp];
    int end = g_rowptr[warp + 1];

    for (; e + 4 <= end; e += 4) {
        int s0 = __ldg(&g_csrc[e]);
        int s1 = __ldg(&g_csrc[e + 1]);
        int s2 = __ldg(&g_csrc[e + 2]);
        int s3 = __ldg(&g_csrc[e + 3]);
        float w0 = scale_src ? __ldg(&g_dinv[s0]) : 1.f;
        float w1 = scale_src ? __ldg(&g_dinv[s1]) : 1.f;
        float w2 = scale_src ? __ldg(&g_dinv[s2]) : 1.f;
        float w3 = scale_src ? __ldg(&g_dinv[s3]) : 1.f;
        float4 v0 = y4[s0 * 32 + lane];
        float4 v1 = y4[s1 * 32 + lane];
        float4 v2 = y4[s2 * 32 + lane];
        float4 v3 = y4[s3 * 32 + lane];
        acc0.x = fmaf(w0, v0.x, acc0.x); acc0.y = fmaf(w0, v0.y, acc0.y);
        acc0.z = fmaf(w0, v0.z, acc0.z); acc0.w = fmaf(w0, v0.w, acc0.w);
        acc1.x = fmaf(w1, v1.x, acc1.x); acc1.y = fmaf(w1, v1.y, acc1.y);
        acc1.z = fmaf(w1, v1.z, acc1.z); acc1.w = fmaf(w1, v1.w, acc1.w);
        acc0.x = fmaf(w2, v2.x, acc0.x); acc0.y = fmaf(w2, v2.y, acc0.y);
        acc0.z = fmaf(w2, v2.z, acc0.z); acc0.w = fmaf(w2, v2.w, acc0.w);
        acc1.x = fmaf(w3, v3.x, acc1.x); acc1.y = fmaf(w3, v3.y, acc1.y);
        acc1.z = fmaf(w3, v3.z, acc1.z); acc1.w = fmaf(w3, v3.w, acc1.w);
    }
    for (; e < end; e++) {
        int s = __ldg(&g_csrc[e]);
        float w = scale_src ? __ldg(&g_dinv[s]) : 1.f;
        float4 v = y4[s * 32 + lane];
        acc0.x = fmaf(w, v.x, acc0.x); acc0.y = fmaf(w, v.y, acc0.y);
        acc0.z = fmaf(w, v.z, acc0.z); acc0.w = fmaf(w, v.w, acc0.w);
    }

    acc0.x += acc1.x; acc0.y += acc1.y; acc0.z += acc1.z; acc0.w += acc1.w;

    float4 b = bias ? reinterpret_cast<const float4*>(bias)[lane]
                    : make_float4(0.f, 0.f, 0.f, 0.f);
    float4 r;
    r.x = fmaf(di, acc0.x, b.x);
    r.y = fmaf(di, acc0.y, b.y);
    r.z = fmaf(di, acc0.z, b.z);
    r.w = fmaf(di, acc0.w, b.w);
    if (do_relu) {
        r.x = fmaxf(r.x, 0.f); r.y = fmaxf(r.y, 0.f);
        r.z = fmaxf(r.z, 0.f); r.w = fmaxf(r.w, 0.f);
    }
    reinterpret_cast<float4*>(out)[warp * 32 + lane] = r;
}

// ---------------- mean pool over sorted batch ---------------------------------
__global__ __launch_bounds__(128) void pool_kernel(const int* __restrict__ batch,
                                                   const float* __restrict__ h)
{
    int g = blockIdx.x;
    __shared__ int s_beg, s_end;
    if (threadIdx.x == 0) {
        int lo = 0, hi = N_NODES;
        while (lo < hi) { int m = (lo + hi) >> 1; if (batch[m] < g) lo = m + 1; else hi = m; }
        s_beg = lo;
        lo = 0; hi = N_NODES;
        while (lo < hi) { int m = (lo + hi) >> 1; if (batch[m] < g + 1) lo = m + 1; else hi = m; }
        s_end = lo;
    }
    __syncthreads();
    int f = threadIdx.x;
    float sum = 0.f;
    for (int n = s_beg; n < s_end; n++) sum += h[n * 128 + f];
    float cnt = (float)(s_end - s_beg);
    g_s[g * 128 + f] = sum / fmaxf(cnt, 1.0f);
}

// ---------------- head fold: WC = W3@Wl, bc = b3@Wl + bl ----------------------
__global__ void head_fold_kernel(const float* __restrict__ W3, const float* __restrict__ b3,
                                 const float* __restrict__ Wl, const float* __restrict__ bl)
{
    int t = threadIdx.x;
    if (t < HIDDEN * N_CLASSES) {
        int j = t / N_CLASSES, c = t % N_CLASSES;
        float s = 0.f;
        for (int k = 0; k < HIDDEN; k++) s = fmaf(W3[j * HIDDEN + k], Wl[k * N_CLASSES + c], s);
        g_WC[t] = s;
    } else if (t < HIDDEN * N_CLASSES + N_CLASSES) {
        int c = t - HIDDEN * N_CLASSES;
        float s = bl[c];
        for (int k = 0; k < HIDDEN; k++) s = fmaf(b3[k], Wl[k * N_CLASSES + c], s);
        g_bc[c] = s;
    }
}

// ---------------- out[g,c] = s[g,:] @ WC[:,c] + bc[c] -------------------------
__global__ void out_kernel(float* __restrict__ out) {
    int t = blockIdx.x * blockDim.x + threadIdx.x;
    if (t < N_GRAPHS * N_CLASSES) {
        int g = t / N_CLASSES, c = t % N_CLASSES;
        float s = g_bc[c];
        for (int k = 0; k < HIDDEN; k++) s = fmaf(g_s[g * 128 + k], g_WC[k * N_CLASSES + c], s);
        out[t] = s;
    }
}

// ---------------- launcher ----------------------------------------------------
extern "C" void kernel_launch(void* const* d_in, const int* in_sizes, int n_in,
                              void* d_out, int out_size)
{
    const float* x     = (const float*)d_in[0];
    const int*   ei    = (const int*)  d_in[1];
    const int*   batch = (const int*)  d_in[2];
    const float* W1    = (const float*)d_in[3];
    const float* b1    = (const float*)d_in[4];
    const float* W2    = (const float*)d_in[5];
    const float* b2    = (const float*)d_in[6];
    const float* W3    = (const float*)d_in[7];
    const float* b3    = (const float*)d_in[8];
    const float* Wl    = (const float*)d_in[9];
    const float* bl    = (const float*)d_in[10];
    float* out = (float*)d_out;

    float *yb, *hb;
    void* degPtr;
    void* wfragPtr;
    cudaGetSymbolAddress((void**)&yb, g_y);
    cudaGetSymbolAddress((void**)&hb, g_h);
    cudaGetSymbolAddress(&degPtr, g_deg);
    cudaGetSymbolAddress(&wfragPtr, g_wfrag);
    const float4* wf1 = (const float4*)wfragPtr;
    const float4* wf2 = wf1 + 8192;

    const int EB4 = (N_EDGES / 4 + 255) / 256;
    const int GEMM_BLOCKS = (N_NODES + 127) / 128;   // 313
    const int AGG_BLOCKS  = (N_NODES + 7) / 8;

    // CSR build + W fragment precompute (independent)
    cudaMemsetAsync(degPtr, 0, N_NODES * sizeof(int));
    wfrag_kernel<<<(2 * 8192 + 255) / 256, 256>>>(W1, W2);
    count_deg_kernel<<<EB4, 256>>>(ei);
    scan_kernel<<<1, 1024>>>();
    fill_csr_kernel<<<EB4, 256>>>(ei);

    // layer 1
    gemm_tf32_kernel<<<GEMM_BLOCKS, 256>>>(x, wf1, yb);
    agg_kernel<<<AGG_BLOCKS, 256>>>(yb, hb, b1, 1, 0);
    // layer 2
    gemm_tf32_kernel<<<GEMM_BLOCKS, 256>>>(hb, wf2, yb);
    agg_kernel<<<AGG_BLOCKS, 256>>>(yb, hb, b2, 1, 0);
    // layer 3 (reassociated; dinv[src] fused into gather)
    agg_kernel<<<AGG_BLOCKS, 256>>>(hb, yb, (const float*)nullptr, 0, 1);

    // pool + folded head
    pool_kernel<<<N_GRAPHS, 128>>>(batch, yb);
    head_fold_kernel<<<1, HIDDEN * N_CLASSES + N_CLASSES>>>(W3, b3, Wl, bl);
    out_kernel<<<(N_GRAPHS * N_CLASSES + 255) / 256, 256>>>(out);
}

// round 8
// speedup vs baseline: 1.2309x; 1.0462x over previous
#include <cuda_runtime.h>
#include <cuda_bf16.h>
#include <cstdint>

#define N_NODES 40000
#define N_EDGES 640000
#define HIDDEN  128
#define N_GRAPHS 256
#define N_CLASSES 5

#define GEMM_BLOCKS 313          // ceil(40000/128)
#define EB8 313                  // ceil(640000/8/256)

// ---------------- scratch (static device globals; no runtime alloc) ----------
__device__ __align__(16) float g_y[N_NODES * HIDDEN];   // GEMM output (gather source)
__device__ __align__(16) float g_h[N_NODES * HIDDEN];   // aggregated / activated features
__device__ __align__(16) float g_dinv[N_NODES];
__device__ __align__(16) int   g_deg[N_NODES];
__device__ __align__(16) int   g_rowptr[N_NODES + 4];
__device__ __align__(16) int   g_cursor[N_NODES];
__device__ __align__(16) int   g_csrc[N_EDGES];
__device__ float g_s[N_GRAPHS * HIDDEN];    // pooled means
__device__ float g_WC[HIDDEN * N_CLASSES];  // W3 @ Wl
__device__ float g_bc[N_CLASSES];           // b3 @ Wl + bl
// Precomputed W fragments for tf32 MMA, per layer:
// [ (ks*16 + nt)*32 + lane ] -> float4 { b0_hi, b1_hi, b0_lo, b1_lo }
__device__ __align__(16) float g_wfrag[2][16 * 16 * 32 * 4];

// ---------------- tf32 helpers ------------------------------------------------
__device__ __forceinline__ unsigned f2tf32(float f) {
    unsigned u;
    asm("cvt.rna.tf32.f32 %0, %1;" : "=r"(u) : "f"(f));
    return u;
}

__device__ __forceinline__ void mma_tf32(float* d,
                                         unsigned a0, unsigned a1, unsigned a2, unsigned a3,
                                         unsigned b0, unsigned b1)
{
    asm volatile(
        "mma.sync.aligned.m16n8k8.row.col.f32.tf32.tf32.f32 "
        "{%0,%1,%2,%3}, {%4,%5,%6,%7}, {%8,%9}, {%0,%1,%2,%3};"
        : "+f"(d[0]), "+f"(d[1]), "+f"(d[2]), "+f"(d[3])
        : "r"(a0), "r"(a1), "r"(a2), "r"(a3), "r"(b0), "r"(b1));
}

// ---------------- GEMM body (tf32 split precision), callable per-block --------
// Y = A @ W (raw). dinv handling lives entirely in aggregation.
__device__ __forceinline__ void gemm_body(int bid, const float* __restrict__ A,
                                          const float4* __restrict__ wfrag,
                                          float* __restrict__ Y)
{
    __shared__ __align__(16) float s_a[128 * 68];   // 128 rows x 64 k-cols, pad 4

    int tid  = threadIdx.x;
    int warp = tid >> 5;
    int lane = tid & 31;
    int row0 = bid * 128;
    int wrow = row0 + warp * 16;

    float acc[64];
    #pragma unroll
    for (int i = 0; i < 64; i++) acc[i] = 0.f;

    const uint4* bf = reinterpret_cast<const uint4*>(wfrag);

    #pragma unroll
    for (int kh = 0; kh < 2; kh++) {
        #pragma unroll
        for (int j = 0; j < 8; j++) {
            int idx = tid + 256 * j;            // 0..2047
            int r = idx >> 4;                   // 0..127
            int c = (idx & 15) * 4;             // 0..60
            int gr = row0 + r;
            float4 v = make_float4(0.f, 0.f, 0.f, 0.f);
            if (gr < N_NODES)
                v = *reinterpret_cast<const float4*>(&A[gr * 128 + kh * 64 + c]);
            *reinterpret_cast<float4*>(&s_a[r * 68 + c]) = v;
        }
        __syncthreads();

        #pragma unroll
        for (int ksl = 0; ksl < 8; ksl++) {
            int ks = kh * 8 + ksl;
            int c  = ksl * 8 + (lane & 3);
            int rA = warp * 16 + (lane >> 2);
            float f0 = s_a[rA * 68 + c];
            float f1 = s_a[(rA + 8) * 68 + c];
            float f2 = s_a[rA * 68 + c + 4];
            float f3 = s_a[(rA + 8) * 68 + c + 4];
            unsigned ah0 = f2tf32(f0), ah1 = f2tf32(f1), ah2 = f2tf32(f2), ah3 = f2tf32(f3);
            unsigned al0 = f2tf32(f0 - __uint_as_float(ah0));
            unsigned al1 = f2tf32(f1 - __uint_as_float(ah1));
            unsigned al2 = f2tf32(f2 - __uint_as_float(ah2));
            unsigned al3 = f2tf32(f3 - __uint_as_float(ah3));

            const uint4* bk = bf + ks * (16 * 32) + lane;
            #pragma unroll
            for (int nt = 0; nt < 16; nt++) {
                uint4 b = __ldg(bk + nt * 32);   // {b0_hi, b1_hi, b0_lo, b1_lo}
                float* d = acc + nt * 4;
                mma_tf32(d, ah0, ah1, ah2, ah3, b.x, b.y);  // hi*hi
                mma_tf32(d, ah0, ah1, ah2, ah3, b.z, b.w);  // hi*lo
                mma_tf32(d, al0, al1, al2, al3, b.x, b.y);  // lo*hi
            }
        }
        __syncthreads();
    }

    if (wrow < N_NODES) {
        int r0 = wrow + (lane >> 2);
        int r1 = r0 + 8;
        #pragma unroll
        for (int nt = 0; nt < 16; nt++) {
            int col = nt * 8 + (lane & 3) * 2;
            float2 o0 = make_float2(acc[nt * 4 + 0], acc[nt * 4 + 1]);
            float2 o1 = make_float2(acc[nt * 4 + 2], acc[nt * 4 + 3]);
            *reinterpret_cast<float2*>(&Y[r0 * 128 + col]) = o0;
            *reinterpret_cast<float2*>(&Y[r1 * 128 + col]) = o1;
        }
    }
}

// ---------------- fused: wfrag precompute + deg memset ------------------------
// blocks [0,64): wfrag (16384 threads); blocks [64,104): zero g_deg (int4)
__global__ __launch_bounds__(256) void wfrag_memset_kernel(
    const float* __restrict__ W1, const float* __restrict__ W2)
{
    if (blockIdx.x < 64) {
        int t = blockIdx.x * 256 + threadIdx.x;     // 0..16383
        int layer = t >> 13;
        int r = t & 8191;                 // (ks*16 + nt)*32 + lane
        int ks   = r >> 9;
        int lane = r & 31;
        int k0 = ks * 8 + (lane & 3);
        int n  = ((r >> 5) & 15) * 8 + (lane >> 2);
        const float* W = layer ? W2 : W1;
        float b0 = W[k0 * HIDDEN + n];
        float b1 = W[(k0 + 4) * HIDDEN + n];
        unsigned h0 = f2tf32(b0);
        unsigned h1 = f2tf32(b1);
        unsigned l0 = f2tf32(b0 - __uint_as_float(h0));
        unsigned l1 = f2tf32(b1 - __uint_as_float(h1));
        float4 o = make_float4(__uint_as_float(h0), __uint_as_float(h1),
                               __uint_as_float(l0), __uint_as_float(l1));
        *reinterpret_cast<float4*>(&g_wfrag[layer][r * 4]) = o;
    } else {
        int t = (blockIdx.x - 64) * 256 + threadIdx.x;  // int4 index, 0..9999
        if (t < N_NODES / 4)
            *reinterpret_cast<int4*>(&g_deg[t * 4]) = make_int4(0, 0, 0, 0);
    }
}

// ---------------- fused: GEMM layer-1 + degree count --------------------------
// blocks [0,GEMM_BLOCKS): GEMM1; blocks [GEMM_BLOCKS, GEMM_BLOCKS+EB8): count
__global__ __launch_bounds__(256) void gemm1_count_kernel(
    const float* __restrict__ A, const float4* __restrict__ wfrag,
    float* __restrict__ Y, const int* __restrict__ ei)
{
    if (blockIdx.x < GEMM_BLOCKS) {
        gemm_body(blockIdx.x, A, wfrag, Y);
    } else {
        int e8 = ((blockIdx.x - GEMM_BLOCKS) * 256 + threadIdx.x) * 8;
        if (e8 < N_EDGES) {   // N_EDGES % 8 == 0
            int4 d0 = *reinterpret_cast<const int4*>(&ei[N_EDGES + e8]);
            int4 d1 = *reinterpret_cast<const int4*>(&ei[N_EDGES + e8 + 4]);
            atomicAdd(&g_deg[d0.x], 1);
            atomicAdd(&g_deg[d0.y], 1);
            atomicAdd(&g_deg[d0.z], 1);
            atomicAdd(&g_deg[d0.w], 1);
            atomicAdd(&g_deg[d1.x], 1);
            atomicAdd(&g_deg[d1.y], 1);
            atomicAdd(&g_deg[d1.z], 1);
            atomicAdd(&g_deg[d1.w], 1);
        }
    }
}

// ---------------- standalone GEMM (layer 2) -----------------------------------
__global__ __launch_bounds__(256) void gemm_tf32_kernel(
    const float* __restrict__ A, const float4* __restrict__ wfrag,
    float* __restrict__ Y)
{
    gemm_body(blockIdx.x, A, wfrag, Y);
}

// ---------------- scan: rowptr/cursor/dinv from deg ---------------------------
__global__ void scan_kernel() {
    const int NT = 1024;
    int tid = threadIdx.x;
    int lane = tid & 31, wid = tid >> 5;
    __shared__ int wsum[32];
    __shared__ int s_carry;
    if (tid == 0) s_carry = 0;
    __syncthreads();
    for (int base = 0; base < N_NODES; base += NT * 4) {
        int i4 = base + tid * 4;
        int4 v = make_int4(0, 0, 0, 0);
        if (i4 < N_NODES)
            v = *reinterpret_cast<const int4*>(&g_deg[i4]);
        int s = v.x + v.y + v.z + v.w;
        int x = s;
        #pragma unroll
        for (int d = 1; d < 32; d <<= 1) {
            int t = __shfl_up_sync(0xffffffffu, x, d);
            if (lane >= d) x += t;
        }
        if (lane == 31) wsum[wid] = x;
        __syncthreads();
        if (wid == 0) {
            int w = wsum[lane];
            #pragma unroll
            for (int d = 1; d < 32; d <<= 1) {
                int t = __shfl_up_sync(0xffffffffu, w, d);
                if (lane >= d) w += t;
            }
            wsum[lane] = w;
        }
        __syncthreads();
        int carry = s_carry;
        int woff = (wid == 0) ? 0 : wsum[wid - 1];
        int incl = x + woff + carry;
        int e0 = incl - s;
        if (i4 < N_NODES) {
            int4 rp = make_int4(e0, e0 + v.x, e0 + v.x + v.y, e0 + v.x + v.y + v.z);
            *reinterpret_cast<int4*>(&g_rowptr[i4]) = rp;
            *reinterpret_cast<int4*>(&g_cursor[i4]) = rp;
            float4 dv = make_float4(rsqrtf((float)(v.x + 1)), rsqrtf((float)(v.y + 1)),
                                    rsqrtf((float)(v.z + 1)), rsqrtf((float)(v.w + 1)));
            *reinterpret_cast<float4*>(&g_dinv[i4]) = dv;
        }
        __syncthreads();
        if (tid == NT - 1) s_carry = incl;
        __syncthreads();
    }
    if (tid == 0) g_rowptr[N_NODES] = s_carry;
}

// ---------------- fused: CSR fill + head fold ---------------------------------
// blocks [0,EB8): fill; blocks [EB8, EB8+3): head fold (WC = W3@Wl, bc = b3@Wl+bl)
__global__ __launch_bounds__(256) void fill_head_kernel(
    const int* __restrict__ ei,
    const float* __restrict__ W3, const float* __restrict__ b3,
    const float* __restrict__ Wl, const float* __restrict__ bl)
{
    if (blockIdx.x < EB8) {
        int e8 = (blockIdx.x * 256 + threadIdx.x) * 8;
        if (e8 < N_EDGES) {
            int4 s0 = *reinterpret_cast<const int4*>(&ei[e8]);
            int4 s1 = *reinterpret_cast<const int4*>(&ei[e8 + 4]);
            int4 d0 = *reinterpret_cast<const int4*>(&ei[N_EDGES + e8]);
            int4 d1 = *reinterpret_cast<const int4*>(&ei[N_EDGES + e8 + 4]);
            int p0 = atomicAdd(&g_cursor[d0.x], 1);
            int p1 = atomicAdd(&g_cursor[d0.y], 1);
            int p2 = atomicAdd(&g_cursor[d0.z], 1);
            int p3 = atomicAdd(&g_cursor[d0.w], 1);
            int p4 = atomicAdd(&g_cursor[d1.x], 1);
            int p5 = atomicAdd(&g_cursor[d1.y], 1);
            int p6 = atomicAdd(&g_cursor[d1.z], 1);
            int p7 = atomicAdd(&g_cursor[d1.w], 1);
            g_csrc[p0] = s0.x;
            g_csrc[p1] = s0.y;
            g_csrc[p2] = s0.z;
            g_csrc[p3] = s0.w;
            g_csrc[p4] = s1.x;
            g_csrc[p5] = s1.y;
            g_csrc[p6] = s1.z;
            g_csrc[p7] = s1.w;
        }
    } else {
        int t = (blockIdx.x - EB8) * 256 + threadIdx.x;
        if (t < HIDDEN * N_CLASSES) {
            int j = t / N_CLASSES, c = t % N_CLASSES;
            float s = 0.f;
            for (int k = 0; k < HIDDEN; k++) s = fmaf(W3[j * HIDDEN + k], Wl[k * N_CLASSES + c], s);
            g_WC[t] = s;
        } else if (t < HIDDEN * N_CLASSES + N_CLASSES) {
            int c = t - HIDDEN * N_CLASSES;
            float s = bl[c];
            for (int k = 0; k < HIDDEN; k++) s = fmaf(b3[k], Wl[k * N_CLASSES + c], s);
            g_bc[c] = s;
        }
    }
}

// ---------------- Aggregation -------------------------------------------------
// out[i] = act( dinv[i] * ( dinv[i]*y[i] + sum_{src} dinv[src]*y[src] ) + b )
__global__ __launch_bounds__(256) void agg_kernel(
    const float* __restrict__ y, float* __restrict__ out,
    const float* __restrict__ bias, int do_relu)
{
    int warp = (blockIdx.x * blockDim.x + threadIdx.x) >> 5;
    int lane = threadIdx.x & 31;
    if (warp >= N_NODES) return;

    const float4* y4 = reinterpret_cast<const float4*>(y);
    float di = g_dinv[warp];

    float4 self = y4[warp * 32 + lane];
    float4 acc0 = make_float4(di * self.x, di * self.y, di * self.z, di * self.w);
    float4 acc1 = make_float4(0.f, 0.f, 0.f, 0.f);

    int e   = g_rowptr[warp];
    int end = g_rowptr[warp + 1];

    for (; e + 4 <= end; e += 4) {
        int s0 = __ldg(&g_csrc[e]);
        int s1 = __ldg(&g_csrc[e + 1]);
        int s2 = __ldg(&g_csrc[e + 2]);
        int s3 = __ldg(&g_csrc[e + 3]);
        float w0 = __ldg(&g_dinv[s0]);
        float w1 = __ldg(&g_dinv[s1]);
        float w2 = __ldg(&g_dinv[s2]);
        float w3 = __ldg(&g_dinv[s3]);
        float4 v0 = y4[s0 * 32 + lane];
        float4 v1 = y4[s1 * 32 + lane];
        float4 v2 = y4[s2 * 32 + lane];
        float4 v3 = y4[s3 * 32 + lane];
        acc0.x = fmaf(w0, v0.x, acc0.x); acc0.y = fmaf(w0, v0.y, acc0.y);
        acc0.z = fmaf(w0, v0.z, acc0.z); acc0.w = fmaf(w0, v0.w, acc0.w);
        acc1.x = fmaf(w1, v1.x, acc1.x); acc1.y = fmaf(w1, v1.y, acc1.y);
        acc1.z = fmaf(w1, v1.z, acc1.z); acc1.w = fmaf(w1, v1.w, acc1.w);
        acc0.x = fmaf(w2, v2.x, acc0.x); acc0.y = fmaf(w2, v2.y, acc0.y);
        acc0.z = fmaf(w2, v2.z, acc0.z); acc0.w = fmaf(w2, v2.w, acc0.w);
        acc1.x = fmaf(w3, v3.x, acc1.x); acc1.y = fmaf(w3, v3.y, acc1.y);
        acc1.z = fmaf(w3, v3.z, acc1.z); acc1.w = fmaf(w3, v3.w, acc1.w);
    }
    for (; e < end; e++) {
        int s = __ldg(&g_csrc[e]);
        float w = __ldg(&g_dinv[s]);
        float4 v = y4[s * 32 + lane];
        acc0.x = fmaf(w, v.x, acc0.x); acc0.y = fmaf(w, v.y, acc0.y);
        acc0.z = fmaf(w, v.z, acc0.z); acc0.w = fmaf(w, v.w, acc0.w);
    }

    acc0.x += acc1.x; acc0.y += acc1.y; acc0.z += acc1.z; acc0.w += acc1.w;

    float4 b = bias ? reinterpret_cast<const float4*>(bias)[lane]
                    : make_float4(0.f, 0.f, 0.f, 0.f);
    float4 r;
    r.x = fmaf(di, acc0.x, b.x);
    r.y = fmaf(di, acc0.y, b.y);
    r.z = fmaf(di, acc0.z, b.z);
    r.w = fmaf(di, acc0.w, b.w);
    if (do_relu) {
        r.x = fmaxf(r.x, 0.f); r.y = fmaxf(r.y, 0.f);
        r.z = fmaxf(r.z, 0.f); r.w = fmaxf(r.w, 0.f);
    }
    reinterpret_cast<float4*>(out)[warp * 32 + lane] = r;
}

// ---------------- mean pool over sorted batch ---------------------------------
__global__ __launch_bounds__(128) void pool_kernel(const int* __restrict__ batch,
                                                   const float* __restrict__ h)
{
    int g = blockIdx.x;
    __shared__ int s_beg, s_end;
    if (threadIdx.x == 0) {
        int lo = 0, hi = N_NODES;
        while (lo < hi) { int m = (lo + hi) >> 1; if (batch[m] < g) lo = m + 1; else hi = m; }
        s_beg = lo;
        lo = 0; hi = N_NODES;
        while (lo < hi) { int m = (lo + hi) >> 1; if (batch[m] < g + 1) lo = m + 1; else hi = m; }
        s_end = lo;
    }
    __syncthreads();
    int f = threadIdx.x;
    float sum = 0.f;
    for (int n = s_beg; n < s_end; n++) sum += h[n * 128 + f];
    float cnt = (float)(s_end - s_beg);
    g_s[g * 128 + f] = sum / fmaxf(cnt, 1.0f);
}

// ---------------- out[g,c] = s[g,:] @ WC[:,c] + bc[c] -------------------------
__global__ void out_kernel(float* __restrict__ out) {
    int t = blockIdx.x * blockDim.x + threadIdx.x;
    if (t < N_GRAPHS * N_CLASSES) {
        int g = t / N_CLASSES, c = t % N_CLASSES;
        float s = g_bc[c];
        for (int k = 0; k < HIDDEN; k++) s = fmaf(g_s[g * 128 + k], g_WC[k * N_CLASSES + c], s);
        out[t] = s;
    }
}

// ---------------- launcher (single stream, block-specialized fusion) ----------
extern "C" void kernel_launch(void* const* d_in, const int* in_sizes, int n_in,
                              void* d_out, int out_size)
{
    const float* x     = (const float*)d_in[0];
    const int*   ei    = (const int*)  d_in[1];
    const int*   batch = (const int*)  d_in[2];
    const float* W1    = (const float*)d_in[3];
    const float* b1    = (const float*)d_in[4];
    const float* W2    = (const float*)d_in[5];
    const float* b2    = (const float*)d_in[6];
    const float* W3    = (const float*)d_in[7];
    const float* b3    = (const float*)d_in[8];
    const float* Wl    = (const float*)d_in[9];
    const float* bl    = (const float*)d_in[10];
    float* out = (float*)d_out;

    float *yb, *hb;
    void* wfragPtr;
    cudaGetSymbolAddress((void**)&yb, g_y);
    cudaGetSymbolAddress((void**)&hb, g_h);
    cudaGetSymbolAddress(&wfragPtr, g_wfrag);
    const float4* wf1 = (const float4*)wfragPtr;
    const float4* wf2 = wf1 + 8192;

    const int AGG_BLOCKS = (N_NODES + 7) / 8;

    // prep: wfrag + deg=0 (fused), then GEMM1 || count (fused), scan, fill+head
    wfrag_memset_kernel<<<64 + 40, 256>>>(W1, W2);
    gemm1_count_kernel<<<GEMM_BLOCKS + EB8, 256>>>(x, wf1, yb, ei);
    scan_kernel<<<1, 1024>>>();
    fill_head_kernel<<<EB8 + 3, 256>>>(ei, W3, b3, Wl, bl);

    // layer 1 (dinv fully inside agg)
    agg_kernel<<<AGG_BLOCKS, 256>>>(yb, hb, b1, 1);
    // layer 2
    gemm_tf32_kernel<<<GEMM_BLOCKS, 256>>>(hb, wf2, yb);
    agg_kernel<<<AGG_BLOCKS, 256>>>(yb, hb, b2, 1);
    // layer 3 (reassociated; GEMM folded into head after pooling)
    agg_kernel<<<AGG_BLOCKS, 256>>>(hb, yb, (const float*)nullptr, 0);

    // pool + folded head
    pool_kernel<<<N_GRAPHS, 128>>>(batch, yb);
    out_kernel<<<(N_GRAPHS * N_CLASSES + 255) / 256, 256>>>(out);
}

// round 9
// speedup vs baseline: 1.2377x; 1.0055x over previous
#include <cuda_runtime.h>
#include <cuda_bf16.h>
#include <cuda_fp16.h>
#include <cstdint>

#define N_NODES 40000
#define N_EDGES 640000
#define HIDDEN  128
#define N_GRAPHS 256
#define N_CLASSES 5

#define GEMM_BLOCKS 313          // ceil(40000/128)
#define CNT_BLOCKS  625          // 640000/4/256
#define FILL_BLOCKS 1250         // 640000/2/256

// ---------------- scratch (static device globals; no runtime alloc) ----------
__device__ __align__(16) float  g_h[N_NODES * HIDDEN];    // h1 fp32 (gemm2 input); z3 fp32
__device__ __align__(16) float  g_z[N_NODES * HIDDEN];    // z3 fp32 (pool input)
__device__ __align__(16) __half g_y16[N_NODES * HIDDEN];  // y1 / y2 fp16 (gather source)
__device__ __align__(16) __half g_h16[N_NODES * HIDDEN];  // h2 fp16 (gather source)
__device__ __align__(16) float  g_dinv[N_NODES];
__device__ __align__(16) int    g_deg[N_NODES];
__device__ __align__(16) int    g_rowptr[N_NODES + 4];
__device__ __align__(16) int    g_cursor[N_NODES];
__device__ __align__(16) int    g_csrc[N_EDGES];
__device__ float g_s[N_GRAPHS * HIDDEN];    // pooled means
__device__ float g_WC[HIDDEN * N_CLASSES];  // W3 @ Wl
__device__ float g_bc[N_CLASSES];           // b3 @ Wl + bl
// Precomputed W fragments for tf32 MMA, per layer:
// [ (ks*16 + nt)*32 + lane ] -> float4 { b0_hi, b1_hi, b0_lo, b1_lo }
__device__ __align__(16) float g_wfrag[2][16 * 16 * 32 * 4];

// ---------------- tf32 helpers ------------------------------------------------
__device__ __forceinline__ unsigned f2tf32(float f) {
    unsigned u;
    asm("cvt.rna.tf32.f32 %0, %1;" : "=r"(u) : "f"(f));
    return u;
}

__device__ __forceinline__ void mma_tf32(float* d,
                                         unsigned a0, unsigned a1, unsigned a2, unsigned a3,
                                         unsigned b0, unsigned b1)
{
    asm volatile(
        "mma.sync.aligned.m16n8k8.row.col.f32.tf32.tf32.f32 "
        "{%0,%1,%2,%3}, {%4,%5,%6,%7}, {%8,%9}, {%0,%1,%2,%3};"
        : "+f"(d[0]), "+f"(d[1]), "+f"(d[2]), "+f"(d[3])
        : "r"(a0), "r"(a1), "r"(a2), "r"(a3), "r"(b0), "r"(b1));
}

// ---------------- GEMM body (tf32 split precision) -> fp16 output -------------
// Y16 = half(A @ W). dinv handling lives entirely in aggregation.
__device__ __forceinline__ void gemm_body(int bid, const float* __restrict__ A,
                                          const float4* __restrict__ wfrag,
                                          __half* __restrict__ Y16)
{
    __shared__ __align__(16) float s_a[128 * 68];   // 128 rows x 64 k-cols, pad 4

    int tid  = threadIdx.x;
    int warp = tid >> 5;
    int lane = tid & 31;
    int row0 = bid * 128;
    int wrow = row0 + warp * 16;

    float acc[64];
    #pragma unroll
    for (int i = 0; i < 64; i++) acc[i] = 0.f;

    const uint4* bf = reinterpret_cast<const uint4*>(wfrag);

    #pragma unroll
    for (int kh = 0; kh < 2; kh++) {
        #pragma unroll
        for (int j = 0; j < 8; j++) {
            int idx = tid + 256 * j;            // 0..2047
            int r = idx >> 4;                   // 0..127
            int c = (idx & 15) * 4;             // 0..60
            int gr = row0 + r;
            float4 v = make_float4(0.f, 0.f, 0.f, 0.f);
            if (gr < N_NODES)
                v = *reinterpret_cast<const float4*>(&A[gr * 128 + kh * 64 + c]);
            *reinterpret_cast<float4*>(&s_a[r * 68 + c]) = v;
        }
        __syncthreads();

        #pragma unroll
        for (int ksl = 0; ksl < 8; ksl++) {
            int ks = kh * 8 + ksl;
            int c  = ksl * 8 + (lane & 3);
            int rA = warp * 16 + (lane >> 2);
            float f0 = s_a[rA * 68 + c];
            float f1 = s_a[(rA + 8) * 68 + c];
            float f2 = s_a[rA * 68 + c + 4];
            float f3 = s_a[(rA + 8) * 68 + c + 4];
            unsigned ah0 = f2tf32(f0), ah1 = f2tf32(f1), ah2 = f2tf32(f2), ah3 = f2tf32(f3);
            unsigned al0 = f2tf32(f0 - __uint_as_float(ah0));
            unsigned al1 = f2tf32(f1 - __uint_as_float(ah1));
            unsigned al2 = f2tf32(f2 - __uint_as_float(ah2));
            unsigned al3 = f2tf32(f3 - __uint_as_float(ah3));

            const uint4* bk = bf + ks * (16 * 32) + lane;
            #pragma unroll
            for (int nt = 0; nt < 16; nt++) {
                uint4 b = __ldg(bk + nt * 32);   // {b0_hi, b1_hi, b0_lo, b1_lo}
                float* d = acc + nt * 4;
                mma_tf32(d, ah0, ah1, ah2, ah3, b.x, b.y);  // hi*hi
                mma_tf32(d, ah0, ah1, ah2, ah3, b.z, b.w);  // hi*lo
                mma_tf32(d, al0, al1, al2, al3, b.x, b.y);  // lo*hi
            }
        }
        __syncthreads();
    }

    if (wrow < N_NODES) {
        int r0 = wrow + (lane >> 2);
        int r1 = r0 + 8;
        #pragma unroll
        for (int nt = 0; nt < 16; nt++) {
            int col = nt * 8 + (lane & 3) * 2;
            __half2 p0 = __floats2half2_rn(acc[nt * 4 + 0], acc[nt * 4 + 1]);
            __half2 p1 = __floats2half2_rn(acc[nt * 4 + 2], acc[nt * 4 + 3]);
            *reinterpret_cast<__half2*>(&Y16[r0 * 128 + col]) = p0;
            *reinterpret_cast<__half2*>(&Y16[r1 * 128 + col]) = p1;
        }
    }
}

// ---------------- fused: wfrag precompute + deg memset + head fold ------------
// blocks [0,64): wfrag; [64,104): zero g_deg; [104,107): WC = W3@Wl, bc = b3@Wl+bl
__global__ __launch_bounds__(256) void prep_kernel(
    const float* __restrict__ W1, const float* __restrict__ W2,
    const float* __restrict__ W3, const float* __restrict__ b3,
    const float* __restrict__ Wl, const float* __restrict__ bl)
{
    if (blockIdx.x < 64) {
        int t = blockIdx.x * 256 + threadIdx.x;     // 0..16383
        int layer = t >> 13;
        int r = t & 8191;                 // (ks*16 + nt)*32 + lane
        int ks   = r >> 9;
        int lane = r & 31;
        int k0 = ks * 8 + (lane & 3);
        int n  = ((r >> 5) & 15) * 8 + (lane >> 2);
        const float* W = layer ? W2 : W1;
        float b0 = W[k0 * HIDDEN + n];
        float b1 = W[(k0 + 4) * HIDDEN + n];
        unsigned h0 = f2tf32(b0);
        unsigned h1 = f2tf32(b1);
        unsigned l0 = f2tf32(b0 - __uint_as_float(h0));
        unsigned l1 = f2tf32(b1 - __uint_as_float(h1));
        float4 o = make_float4(__uint_as_float(h0), __uint_as_float(h1),
                               __uint_as_float(l0), __uint_as_float(l1));
        *reinterpret_cast<float4*>(&g_wfrag[layer][r * 4]) = o;
    } else if (blockIdx.x < 104) {
        int t = (blockIdx.x - 64) * 256 + threadIdx.x;  // int4 index, 0..9999
        if (t < N_NODES / 4)
            *reinterpret_cast<int4*>(&g_deg[t * 4]) = make_int4(0, 0, 0, 0);
    } else {
        int t = (blockIdx.x - 104) * 256 + threadIdx.x;
        if (t < HIDDEN * N_CLASSES) {
            int j = t / N_CLASSES, c = t % N_CLASSES;
            float s = 0.f;
            for (int k = 0; k < HIDDEN; k++) s = fmaf(W3[j * HIDDEN + k], Wl[k * N_CLASSES + c], s);
            g_WC[t] = s;
        } else if (t < HIDDEN * N_CLASSES + N_CLASSES) {
            int c = t - HIDDEN * N_CLASSES;
            float s = bl[c];
            for (int k = 0; k < HIDDEN; k++) s = fmaf(b3[k], Wl[k * N_CLASSES + c], s);
            g_bc[c] = s;
        }
    }
}

// ---------------- fused: GEMM layer-1 + degree count (4 edges/thread) ---------
__global__ __launch_bounds__(256) void gemm1_count_kernel(
    const float* __restrict__ A, const float4* __restrict__ wfrag,
    __half* __restrict__ Y16, const int* __restrict__ ei)
{
    if (blockIdx.x < GEMM_BLOCKS) {
        gemm_body(blockIdx.x, A, wfrag, Y16);
    } else {
        int e4 = ((blockIdx.x - GEMM_BLOCKS) * 256 + threadIdx.x) * 4;
        if (e4 < N_EDGES) {
            int4 d = *reinterpret_cast<const int4*>(&ei[N_EDGES + e4]);
            atomicAdd(&g_deg[d.x], 1);
            atomicAdd(&g_deg[d.y], 1);
            atomicAdd(&g_deg[d.z], 1);
            atomicAdd(&g_deg[d.w], 1);
        }
    }
}

// ---------------- standalone GEMM (layer 2) -----------------------------------
__global__ __launch_bounds__(256) void gemm_tf32_kernel(
    const float* __restrict__ A, const float4* __restrict__ wfrag,
    __half* __restrict__ Y16)
{
    gemm_body(blockIdx.x, A, wfrag, Y16);
}

// ---------------- scan: rowptr/cursor/dinv from deg ---------------------------
__global__ void scan_kernel() {
    const int NT = 1024;
    int tid = threadIdx.x;
    int lane = tid & 31, wid = tid >> 5;
    __shared__ int wsum[32];
    __shared__ int s_carry;
    if (tid == 0) s_carry = 0;
    __syncthreads();
    for (int base = 0; base < N_NODES; base += NT * 4) {
        int i4 = base + tid * 4;
        int4 v = make_int4(0, 0, 0, 0);
        if (i4 < N_NODES)
            v = *reinterpret_cast<const int4*>(&g_deg[i4]);
        int s = v.x + v.y + v.z + v.w;
        int x = s;
        #pragma unroll
        for (int d = 1; d < 32; d <<= 1) {
            int t = __shfl_up_sync(0xffffffffu, x, d);
            if (lane >= d) x += t;
        }
        if (lane == 31) wsum[wid] = x;
        __syncthreads();
        if (wid == 0) {
            int w = wsum[lane];
            #pragma unroll
            for (int d = 1; d < 32; d <<= 1) {
                int t = __shfl_up_sync(0xffffffffu, w, d);
                if (lane >= d) w += t;
            }
            wsum[lane] = w;
        }
        __syncthreads();
        int carry = s_carry;
        int woff = (wid == 0) ? 0 : wsum[wid - 1];
        int incl = x + woff + carry;
        int e0 = incl - s;
        if (i4 < N_NODES) {
            int4 rp = make_int4(e0, e0 + v.x, e0 + v.x + v.y, e0 + v.x + v.y + v.z);
            *reinterpret_cast<int4*>(&g_rowptr[i4]) = rp;
            *reinterpret_cast<int4*>(&g_cursor[i4]) = rp;
            float4 dv = make_float4(rsqrtf((float)(v.x + 1)), rsqrtf((float)(v.y + 1)),
                                    rsqrtf((float)(v.z + 1)), rsqrtf((float)(v.w + 1)));
            *reinterpret_cast<float4*>(&g_dinv[i4]) = dv;
        }
        __syncthreads();
        if (tid == NT - 1) s_carry = incl;
        __syncthreads();
    }
    if (tid == 0) g_rowptr[N_NODES] = s_carry;
}

// ---------------- CSR fill (2 edges/thread, wide grid) ------------------------
__global__ __launch_bounds__(256) void fill_csr_kernel(const int* __restrict__ ei) {
    int e2 = (blockIdx.x * 256 + threadIdx.x) * 2;
    if (e2 < N_EDGES) {
        int2 s = *reinterpret_cast<const int2*>(&ei[e2]);
        int2 d = *reinterpret_cast<const int2*>(&ei[N_EDGES + e2]);
        int p0 = atomicAdd(&g_cursor[d.x], 1);
        int p1 = atomicAdd(&g_cursor[d.y], 1);
        g_csrc[p0] = s.x;
        g_csrc[p1] = s.y;
    }
}

// ---------------- Aggregation (fp16 gather, fp32 accumulate) ------------------
// out[i] = act( dinv[i] * ( dinv[i]*y[i] + sum_{src} dinv[src]*y[src] ) + b )
// One warp per node; lane owns 4 features (8 bytes fp16).
__global__ __launch_bounds__(256) void agg_kernel(
    const __half* __restrict__ y16,
    float* __restrict__ out32, __half* __restrict__ out16,
    const float* __restrict__ bias, int do_relu)
{
    int warp = (blockIdx.x * blockDim.x + threadIdx.x) >> 5;
    int lane = threadIdx.x & 31;
    if (warp >= N_NODES) return;

    const uint2* y8 = reinterpret_cast<const uint2*>(y16);   // 4 halves per lane
    float di = g_dinv[warp];

    uint2 sv = y8[warp * 32 + lane];
    float2 sa = __half22float2(*reinterpret_cast<__half2*>(&sv.x));
    float2 sb = __half22float2(*reinterpret_cast<__half2*>(&sv.y));
    float4 acc0 = make_float4(di * sa.x, di * sa.y, di * sb.x, di * sb.y);
    float4 acc1 = make_float4(0.f, 0.f, 0.f, 0.f);

    int e   = g_rowptr[warp];
    int end = g_rowptr[warp + 1];

    for (; e + 4 <= end; e += 4) {
        int s0 = __ldg(&g_csrc[e]);
        int s1 = __ldg(&g_csrc[e + 1]);
        int s2 = __ldg(&g_csrc[e + 2]);
        int s3 = __ldg(&g_csrc[e + 3]);
        float w0 = __ldg(&g_dinv[s0]);
        float w1 = __ldg(&g_dinv[s1]);
        float w2 = __ldg(&g_dinv[s2]);
        float w3 = __ldg(&g_dinv[s3]);
        uint2 v0 = __ldg(&y8[s0 * 32 + lane]);
        uint2 v1 = __ldg(&y8[s1 * 32 + lane]);
        uint2 v2 = __ldg(&y8[s2 * 32 + lane]);
        uint2 v3 = __ldg(&y8[s3 * 32 + lane]);
        float2 a0 = __half22float2(*reinterpret_cast<__half2*>(&v0.x));
        float2 b0 = __half22float2(*reinterpret_cast<__half2*>(&v0.y));
        float2 a1 = __half22float2(*reinterpret_cast<__half2*>(&v1.x));
        float2 b1 = __half22float2(*reinterpret_cast<__half2*>(&v1.y));
        float2 a2 = __half22float2(*reinterpret_cast<__half2*>(&v2.x));
        float2 b2 = __half22float2(*reinterpret_cast<__half2*>(&v2.y));
        float2 a3 = __half22float2(*reinterpret_cast<__half2*>(&v3.x));
        float2 b3 = __half22float2(*reinterpret_cast<__half2*>(&v3.y));
        acc0.x = fmaf(w0, a0.x, acc0.x); acc0.y = fmaf(w0, a0.y, acc0.y);
        acc0.z = fmaf(w0, b0.x, acc0.z); acc0.w = fmaf(w0, b0.y, acc0.w);
        acc1.x = fmaf(w1, a1.x, acc1.x); acc1.y = fmaf(w1, a1.y, acc1.y);
        acc1.z = fmaf(w1, b1.x, acc1.z); acc1.w = fmaf(w1, b1.y, acc1.w);
        acc0.x = fmaf(w2, a2.x, acc0.x); acc0.y = fmaf(w2, a2.y, acc0.y);
        acc0.z = fmaf(w2, b2.x, acc0.z); acc0.w = fmaf(w2, b2.y, acc0.w);
        acc1.x = fmaf(w3, a3.x, acc1.x); acc1.y = fmaf(w3, a3.y, acc1.y);
        acc1.z = fmaf(w3, b3.x, acc1.z); acc1.w = fmaf(w3, b3.y, acc1.w);
    }
    for (; e < end; e++) {
        int s = __ldg(&g_csrc[e]);
        float w = __ldg(&g_dinv[s]);
        uint2 v = __ldg(&y8[s * 32 + lane]);
        float2 a = __half22float2(*reinterpret_cast<__half2*>(&v.x));
        float2 b = __half22float2(*reinterpret_cast<__half2*>(&v.y));
        acc0.x = fmaf(w, a.x, acc0.x); acc0.y = fmaf(w, a.y, acc0.y);
        acc0.z = fmaf(w, b.x, acc0.z); acc0.w = fmaf(w, b.y, acc0.w);
    }

    acc0.x += acc1.x; acc0.y += acc1.y; acc0.z += acc1.z; acc0.w += acc1.w;

    float4 b = bias ? reinterpret_cast<const float4*>(bias)[lane]
                    : make_float4(0.f, 0.f, 0.f, 0.f);
    float4 r;
    r.x = fmaf(di, acc0.x, b.x);
    r.y = fmaf(di, acc0.y, b.y);
    r.z = fmaf(di, acc0.z, b.z);
    r.w = fmaf(di, acc0.w, b.w);
    if (do_relu) {
        r.x = fmaxf(r.x, 0.f); r.y = fmaxf(r.y, 0.f);
        r.z = fmaxf(r.z, 0.f); r.w = fmaxf(r.w, 0.f);
    }
    if (out32)
        reinterpret_cast<float4*>(out32)[warp * 32 + lane] = r;
    if (out16) {
        uint2 o;
        *reinterpret_cast<__half2*>(&o.x) = __floats2half2_rn(r.x, r.y);
        *reinterpret_cast<__half2*>(&o.y) = __floats2half2_rn(r.z, r.w);
        reinterpret_cast<uint2*>(out16)[warp * 32 + lane] = o;
    }
}

// ---------------- mean pool over sorted batch ---------------------------------
__global__ __launch_bounds__(128) void pool_kernel(const int* __restrict__ batch,
                                                   const float* __restrict__ h)
{
    int g = blockIdx.x;
    __shared__ int s_beg, s_end;
    if (threadIdx.x == 0) {
        int lo = 0, hi = N_NODES;
        while (lo < hi) { int m = (lo + hi) >> 1; if (batch[m] < g) lo = m + 1; else hi = m; }
        s_beg = lo;
        lo = 0; hi = N_NODES;
        while (lo < hi) { int m = (lo + hi) >> 1; if (batch[m] < g + 1) lo = m + 1; else hi = m; }
        s_end = lo;
    }
    __syncthreads();
    int f = threadIdx.x;
    float sum = 0.f;
    for (int n = s_beg; n < s_end; n++) sum += h[n * 128 + f];
    float cnt = (float)(s_end - s_beg);
    g_s[g * 128 + f] = sum / fmaxf(cnt, 1.0f);
}

// ---------------- out[g,c] = s[g,:] @ WC[:,c] + bc[c] -------------------------
__global__ void out_kernel(float* __restrict__ out) {
    int t = blockIdx.x * blockDim.x + threadIdx.x;
    if (t < N_GRAPHS * N_CLASSES) {
        int g = t / N_CLASSES, c = t % N_CLASSES;
        float s = g_bc[c];
        for (int k = 0; k < HIDDEN; k++) s = fmaf(g_s[g * 128 + k], g_WC[k * N_CLASSES + c], s);
        out[t] = s;
    }
}

// ---------------- launcher ----------------------------------------------------
extern "C" void kernel_launch(void* const* d_in, const int* in_sizes, int n_in,
                              void* d_out, int out_size)
{
    const float* x     = (const float*)d_in[0];
    const int*   ei    = (const int*)  d_in[1];
    const int*   batch = (const int*)  d_in[2];
    const float* W1    = (const float*)d_in[3];
    const float* b1    = (const float*)d_in[4];
    const float* W2    = (const float*)d_in[5];
    const float* b2    = (const float*)d_in[6];
    const float* W3    = (const float*)d_in[7];
    const float* b3    = (const float*)d_in[8];
    const float* Wl    = (const float*)d_in[9];
    const float* bl    = (const float*)d_in[10];
    float* out = (float*)d_out;

    float *hb, *zb;
    __half *y16, *h16;
    void* wfragPtr;
    cudaGetSymbolAddress((void**)&hb, g_h);
    cudaGetSymbolAddress((void**)&zb, g_z);
    cudaGetSymbolAddress((void**)&y16, g_y16);
    cudaGetSymbolAddress((void**)&h16, g_h16);
    cudaGetSymbolAddress(&wfragPtr, g_wfrag);
    const float4* wf1 = (const float4*)wfragPtr;
    const float4* wf2 = wf1 + 8192;

    const int AGG_BLOCKS = (N_NODES + 7) / 8;

    // prep (wfrag + deg=0 + head fold), GEMM1 || count, scan, fill
    prep_kernel<<<107, 256>>>(W1, W2, W3, b3, Wl, bl);
    gemm1_count_kernel<<<GEMM_BLOCKS + CNT_BLOCKS, 256>>>(x, wf1, y16, ei);
    scan_kernel<<<1, 1024>>>();
    fill_csr_kernel<<<FILL_BLOCKS, 256>>>(ei);

    // layer 1: gather y1 (fp16) -> h1 fp32
    agg_kernel<<<AGG_BLOCKS, 256>>>(y16, hb, (__half*)nullptr, b1, 1);
    // layer 2: gemm h1 -> y2 fp16; gather -> h2 fp16
    gemm_tf32_kernel<<<GEMM_BLOCKS, 256>>>(hb, wf2, y16);
    agg_kernel<<<AGG_BLOCKS, 256>>>(y16, (float*)nullptr, h16, b2, 1);
    // layer 3 (reassociated): gather h2 (fp16) -> z3 fp32
    agg_kernel<<<AGG_BLOCKS, 256>>>(h16, zb, (__half*)nullptr, (const float*)nullptr, 0);

    // pool + folded head
    pool_kernel<<<N_GRAPHS, 128>>>(batch, zb);
    out_kernel<<<(N_GRAPHS * N_CLASSES + 255) / 256, 256>>>(out);
}

// round 10
// speedup vs baseline: 1.2827x; 1.0363x over previous
#include <cuda_runtime.h>
#include <cuda_bf16.h>
#include <cuda_fp16.h>
#include <cstdint>

#define N_NODES 40000
#define N_EDGES 640000
#define HIDDEN  128
#define N_GRAPHS 256
#define N_CLASSES 5

#define GEMM_BLOCKS 313          // ceil(40000/128)
#define CNT_BLOCKS  625          // 640000/4/256
#define FILL_BLOCKS 1250         // 640000/2/256
#define SCALE_BLOCKS 313         // y1 rescale blocks fused into fill kernel

// ---------------- scratch (static device globals; no runtime alloc) ----------
__device__ __align__(16) float  g_h[N_NODES * HIDDEN];    // h1 fp32 (gemm2 input)
__device__ __align__(16) float  g_z[N_NODES * HIDDEN];    // z3 fp32 (pool input)
__device__ __align__(16) __half g_y16[N_NODES * HIDDEN];  // scaled gather source (y1'/y2')
__device__ __align__(16) __half g_h16[N_NODES * HIDDEN];  // scaled h2' (layer-3 source)
__device__ __align__(16) float  g_dinv[N_NODES];
__device__ __align__(16) int    g_deg[N_NODES];
__device__ __align__(16) int    g_rowptr[N_NODES + 4];
__device__ __align__(16) int    g_cursor[N_NODES];
__device__ __align__(16) int    g_csrc[N_EDGES];
__device__ float g_s[N_GRAPHS * HIDDEN];    // pooled means
__device__ float g_WC[HIDDEN * N_CLASSES];  // W3 @ Wl
__device__ float g_bc[N_CLASSES];           // b3 @ Wl + bl
// Precomputed W fragments for tf32 MMA, per layer:
// [ (ks*16 + nt)*32 + lane ] -> float4 { b0_hi, b1_hi, b0_lo, b1_lo }
__device__ __align__(16) float g_wfrag[2][16 * 16 * 32 * 4];

// ---------------- helpers -----------------------------------------------------
__device__ __forceinline__ unsigned f2tf32(float f) {
    unsigned u;
    asm("cvt.rna.tf32.f32 %0, %1;" : "=r"(u) : "f"(f));
    return u;
}

__device__ __forceinline__ void mma_tf32(float* d,
                                         unsigned a0, unsigned a1, unsigned a2, unsigned a3,
                                         unsigned b0, unsigned b1)
{
    asm volatile(
        "mma.sync.aligned.m16n8k8.row.col.f32.tf32.tf32.f32 "
        "{%0,%1,%2,%3}, {%4,%5,%6,%7}, {%8,%9}, {%0,%1,%2,%3};"
        : "+f"(d[0]), "+f"(d[1]), "+f"(d[2]), "+f"(d[3])
        : "r"(a0), "r"(a1), "r"(a2), "r"(a3), "r"(b0), "r"(b1));
}

__device__ __forceinline__ float2 h2f2(unsigned u) {
    __half2 h = *reinterpret_cast<__half2*>(&u);
    return __half22float2(h);
}

// ---------------- GEMM body (tf32 split precision) -> fp16 output -------------
// Y16 = half( (scale ? dinv[row] : 1) * (A @ W) )
__device__ __forceinline__ void gemm_body(int bid, const float* __restrict__ A,
                                          const float4* __restrict__ wfrag,
                                          __half* __restrict__ Y16, int scale)
{
    __shared__ __align__(16) float s_a[128 * 68];   // 128 rows x 64 k-cols, pad 4

    int tid  = threadIdx.x;
    int warp = tid >> 5;
    int lane = tid & 31;
    int row0 = bid * 128;
    int wrow = row0 + warp * 16;

    float acc[64];
    #pragma unroll
    for (int i = 0; i < 64; i++) acc[i] = 0.f;

    const uint4* bf = reinterpret_cast<const uint4*>(wfrag);

    #pragma unroll
    for (int kh = 0; kh < 2; kh++) {
        #pragma unroll
        for (int j = 0; j < 8; j++) {
            int idx = tid + 256 * j;            // 0..2047
            int r = idx >> 4;                   // 0..127
            int c = (idx & 15) * 4;             // 0..60
            int gr = row0 + r;
            float4 v = make_float4(0.f, 0.f, 0.f, 0.f);
            if (gr < N_NODES)
                v = *reinterpret_cast<const float4*>(&A[gr * 128 + kh * 64 + c]);
            *reinterpret_cast<float4*>(&s_a[r * 68 + c]) = v;
        }
        __syncthreads();

        #pragma unroll
        for (int ksl = 0; ksl < 8; ksl++) {
            int ks = kh * 8 + ksl;
            int c  = ksl * 8 + (lane & 3);
            int rA = warp * 16 + (lane >> 2);
            float f0 = s_a[rA * 68 + c];
            float f1 = s_a[(rA + 8) * 68 + c];
            float f2 = s_a[rA * 68 + c + 4];
            float f3 = s_a[(rA + 8) * 68 + c + 4];
            unsigned ah0 = f2tf32(f0), ah1 = f2tf32(f1), ah2 = f2tf32(f2), ah3 = f2tf32(f3);
            unsigned al0 = f2tf32(f0 - __uint_as_float(ah0));
            unsigned al1 = f2tf32(f1 - __uint_as_float(ah1));
            unsigned al2 = f2tf32(f2 - __uint_as_float(ah2));
            unsigned al3 = f2tf32(f3 - __uint_as_float(ah3));

            const uint4* bk = bf + ks * (16 * 32) + lane;
            #pragma unroll
            for (int nt = 0; nt < 16; nt++) {
                uint4 b = __ldg(bk + nt * 32);   // {b0_hi, b1_hi, b0_lo, b1_lo}
                float* d = acc + nt * 4;
                mma_tf32(d, ah0, ah1, ah2, ah3, b.x, b.y);  // hi*hi
                mma_tf32(d, ah0, ah1, ah2, ah3, b.z, b.w);  // hi*lo
                mma_tf32(d, al0, al1, al2, al3, b.x, b.y);  // lo*hi
            }
        }
        __syncthreads();
    }

    if (wrow < N_NODES) {
        int r0 = wrow + (lane >> 2);
        int r1 = r0 + 8;
        float d0 = scale ? g_dinv[r0] : 1.f;
        float d1 = scale ? g_dinv[r1] : 1.f;
        #pragma unroll
        for (int nt = 0; nt < 16; nt++) {
            int col = nt * 8 + (lane & 3) * 2;
            __half2 p0 = __floats2half2_rn(d0 * acc[nt * 4 + 0], d0 * acc[nt * 4 + 1]);
            __half2 p1 = __floats2half2_rn(d1 * acc[nt * 4 + 2], d1 * acc[nt * 4 + 3]);
            *reinterpret_cast<__half2*>(&Y16[r0 * 128 + col]) = p0;
            *reinterpret_cast<__half2*>(&Y16[r1 * 128 + col]) = p1;
        }
    }
}

// ---------------- fused: wfrag precompute + deg memset + head fold ------------
// blocks [0,64): wfrag; [64,104): zero g_deg; [104,107): WC = W3@Wl, bc = b3@Wl+bl
__global__ __launch_bounds__(256) void prep_kernel(
    const float* __restrict__ W1, const float* __restrict__ W2,
    const float* __restrict__ W3, const float* __restrict__ b3,
    const float* __restrict__ Wl, const float* __restrict__ bl)
{
    if (blockIdx.x < 64) {
        int t = blockIdx.x * 256 + threadIdx.x;     // 0..16383
        int layer = t >> 13;
        int r = t & 8191;                 // (ks*16 + nt)*32 + lane
        int ks   = r >> 9;
        int lane = r & 31;
        int k0 = ks * 8 + (lane & 3);
        int n  = ((r >> 5) & 15) * 8 + (lane >> 2);
        const float* W = layer ? W2 : W1;
        float b0 = W[k0 * HIDDEN + n];
        float b1 = W[(k0 + 4) * HIDDEN + n];
        unsigned h0 = f2tf32(b0);
        unsigned h1 = f2tf32(b1);
        unsigned l0 = f2tf32(b0 - __uint_as_float(h0));
        unsigned l1 = f2tf32(b1 - __uint_as_float(h1));
        float4 o = make_float4(__uint_as_float(h0), __uint_as_float(h1),
                               __uint_as_float(l0), __uint_as_float(l1));
        *reinterpret_cast<float4*>(&g_wfrag[layer][r * 4]) = o;
    } else if (blockIdx.x < 104) {
        int t = (blockIdx.x - 64) * 256 + threadIdx.x;  // int4 index, 0..9999
        if (t < N_NODES / 4)
            *reinterpret_cast<int4*>(&g_deg[t * 4]) = make_int4(0, 0, 0, 0);
    } else {
        int t = (blockIdx.x - 104) * 256 + threadIdx.x;
        if (t < HIDDEN * N_CLASSES) {
            int j = t / N_CLASSES, c = t % N_CLASSES;
            float s = 0.f;
            for (int k = 0; k < HIDDEN; k++) s = fmaf(W3[j * HIDDEN + k], Wl[k * N_CLASSES + c], s);
            g_WC[t] = s;
        } else if (t < HIDDEN * N_CLASSES + N_CLASSES) {
            int c = t - HIDDEN * N_CLASSES;
            float s = bl[c];
            for (int k = 0; k < HIDDEN; k++) s = fmaf(b3[k], Wl[k * N_CLASSES + c], s);
            g_bc[c] = s;
        }
    }
}

// ---------------- fused: GEMM layer-1 + degree count (4 edges/thread) ---------
__global__ __launch_bounds__(256) void gemm1_count_kernel(
    const float* __restrict__ A, const float4* __restrict__ wfrag,
    __half* __restrict__ Y16, const int* __restrict__ ei)
{
    if (blockIdx.x < GEMM_BLOCKS) {
        gemm_body(blockIdx.x, A, wfrag, Y16, 0);   // raw (dinv not ready yet)
    } else {
        int e4 = ((blockIdx.x - GEMM_BLOCKS) * 256 + threadIdx.x) * 4;
        if (e4 < N_EDGES) {
            int4 d = *reinterpret_cast<const int4*>(&ei[N_EDGES + e4]);
            atomicAdd(&g_deg[d.x], 1);
            atomicAdd(&g_deg[d.y], 1);
            atomicAdd(&g_deg[d.z], 1);
            atomicAdd(&g_deg[d.w], 1);
        }
    }
}

// ---------------- standalone GEMM (layer 2, epilogue applies dinv) ------------
__global__ __launch_bounds__(256) void gemm_tf32_kernel(
    const float* __restrict__ A, const float4* __restrict__ wfrag,
    __half* __restrict__ Y16)
{
    gemm_body(blockIdx.x, A, wfrag, Y16, 1);
}

// ---------------- scan: rowptr/cursor/dinv from deg ---------------------------
__global__ void scan_kernel() {
    const int NT = 1024;
    int tid = threadIdx.x;
    int lane = tid & 31, wid = tid >> 5;
    __shared__ int wsum[32];
    __shared__ int s_carry;
    if (tid == 0) s_carry = 0;
    __syncthreads();
    for (int base = 0; base < N_NODES; base += NT * 4) {
        int i4 = base + tid * 4;
        int4 v = make_int4(0, 0, 0, 0);
        if (i4 < N_NODES)
            v = *reinterpret_cast<const int4*>(&g_deg[i4]);
        int s = v.x + v.y + v.z + v.w;
        int x = s;
        #pragma unroll
        for (int d = 1; d < 32; d <<= 1) {
            int t = __shfl_up_sync(0xffffffffu, x, d);
            if (lane >= d) x += t;
        }
        if (lane == 31) wsum[wid] = x;
        __syncthreads();
        if (wid == 0) {
            int w = wsum[lane];
            #pragma unroll
            for (int d = 1; d < 32; d <<= 1) {
                int t = __shfl_up_sync(0xffffffffu, w, d);
                if (lane >= d) w += t;
            }
            wsum[lane] = w;
        }
        __syncthreads();
        int carry = s_carry;
        int woff = (wid == 0) ? 0 : wsum[wid - 1];
        int incl = x + woff + carry;
        int e0 = incl - s;
        if (i4 < N_NODES) {
            int4 rp = make_int4(e0, e0 + v.x, e0 + v.x + v.y, e0 + v.x + v.y + v.z);
            *reinterpret_cast<int4*>(&g_rowptr[i4]) = rp;
            *reinterpret_cast<int4*>(&g_cursor[i4]) = rp;
            float4 dv = make_float4(rsqrtf((float)(v.x + 1)), rsqrtf((float)(v.y + 1)),
                                    rsqrtf((float)(v.z + 1)), rsqrtf((float)(v.w + 1)));
            *reinterpret_cast<float4*>(&g_dinv[i4]) = dv;
        }
        __syncthreads();
        if (tid == NT - 1) s_carry = incl;
        __syncthreads();
    }
    if (tid == 0) g_rowptr[N_NODES] = s_carry;
}

// ---------------- fused: CSR fill (2 edges/thread) + y1 dinv rescale ----------
// blocks [0,FILL_BLOCKS): fill; rest: y16[i] *= dinv[node(i)] in place.
// Rescale rides fill's idle issue/BW (fill is atomic-latency-bound).
__global__ __launch_bounds__(256) void fill_scale_kernel(
    const int* __restrict__ ei, __half* __restrict__ y16)
{
    if (blockIdx.x < FILL_BLOCKS) {
        int e2 = (blockIdx.x * 256 + threadIdx.x) * 2;
        if (e2 < N_EDGES) {
            int2 s = *reinterpret_cast<const int2*>(&ei[e2]);
            int2 d = *reinterpret_cast<const int2*>(&ei[N_EDGES + e2]);
            int p0 = atomicAdd(&g_cursor[d.x], 1);
            int p1 = atomicAdd(&g_cursor[d.y], 1);
            g_csrc[p0] = s.x;
            g_csrc[p1] = s.y;
        }
    } else {
        const int TOT = N_NODES * 32;   // uint2 elements (4 halves each)
        const int STRIDE = SCALE_BLOCKS * 256;
        uint2* p = reinterpret_cast<uint2*>(y16);
        for (int i = (blockIdx.x - FILL_BLOCKS) * 256 + threadIdx.x; i < TOT; i += STRIDE) {
            float d = g_dinv[i >> 5];
            uint2 v = p[i];
            float2 a = h2f2(v.x);
            float2 b = h2f2(v.y);
            uint2 o;
            *reinterpret_cast<__half2*>(&o.x) = __floats2half2_rn(d * a.x, d * a.y);
            *reinterpret_cast<__half2*>(&o.y) = __floats2half2_rn(d * b.x, d * b.y);
            p[i] = o;
        }
    }
}

// ---------------- Aggregation (pure fp16 gather-sum) --------------------------
// Rows are pre-scaled by dinv[src]:  r = dinv[i] * sum_{self+in} row[s] + b
// out32: fp32 result (next GEMM / pool input); out16: dinv[i]*r (next gather src)
__global__ __launch_bounds__(256) void agg_kernel(
    const __half* __restrict__ y16,
    float* __restrict__ out32, __half* __restrict__ out16,
    const float* __restrict__ bias, int do_relu)
{
    int warp = (blockIdx.x * blockDim.x + threadIdx.x) >> 5;
    int lane = threadIdx.x & 31;
    if (warp >= N_NODES) return;

    const uint2* y8 = reinterpret_cast<const uint2*>(y16);   // 4 halves per lane
    float di = g_dinv[warp];

    uint2 sv = y8[warp * 32 + lane];
    float2 sa = h2f2(sv.x), sb = h2f2(sv.y);
    float4 acc0 = make_float4(sa.x, sa.y, sb.x, sb.y);
    float4 acc1 = make_float4(0.f, 0.f, 0.f, 0.f);

    int e   = g_rowptr[warp];
    int end = g_rowptr[warp + 1];

    for (; e + 4 <= end; e += 4) {
        int s0 = __ldg(&g_csrc[e]);
        int s1 = __ldg(&g_csrc[e + 1]);
        int s2 = __ldg(&g_csrc[e + 2]);
        int s3 = __ldg(&g_csrc[e + 3]);
        uint2 v0 = __ldg(&y8[s0 * 32 + lane]);
        uint2 v1 = __ldg(&y8[s1 * 32 + lane]);
        uint2 v2 = __ldg(&y8[s2 * 32 + lane]);
        uint2 v3 = __ldg(&y8[s3 * 32 + lane]);
        float2 a0 = h2f2(v0.x), b0 = h2f2(v0.y);
        float2 a1 = h2f2(v1.x), b1 = h2f2(v1.y);
        float2 a2 = h2f2(v2.x), b2 = h2f2(v2.y);
        float2 a3 = h2f2(v3.x), b3 = h2f2(v3.y);
        acc0.x += a0.x; acc0.y += a0.y; acc0.z += b0.x; acc0.w += b0.y;
        acc1.x += a1.x; acc1.y += a1.y; acc1.z += b1.x; acc1.w += b1.y;
        acc0.x += a2.x; acc0.y += a2.y; acc0.z += b2.x; acc0.w += b2.y;
        acc1.x += a3.x; acc1.y += a3.y; acc1.z += b3.x; acc1.w += b3.y;
    }
    for (; e < end; e++) {
        int s = __ldg(&g_csrc[e]);
        uint2 v = __ldg(&y8[s * 32 + lane]);
        float2 a = h2f2(v.x), b = h2f2(v.y);
        acc0.x += a.x; acc0.y += a.y; acc0.z += b.x; acc0.w += b.y;
    }

    acc0.x += acc1.x; acc0.y += acc1.y; acc0.z += acc1.z; acc0.w += acc1.w;

    float4 b = bias ? reinterpret_cast<const float4*>(bias)[lane]
                    : make_float4(0.f, 0.f, 0.f, 0.f);
    float4 r;
    r.x = fmaf(di, acc0.x, b.x);
    r.y = fmaf(di, acc0.y, b.y);
    r.z = fmaf(di, acc0.z, b.z);
    r.w = fmaf(di, acc0.w, b.w);
    if (do_relu) {
        r.x = fmaxf(r.x, 0.f); r.y = fmaxf(r.y, 0.f);
        r.z = fmaxf(r.z, 0.f); r.w = fmaxf(r.w, 0.f);
    }
    if (out32)
        reinterpret_cast<float4*>(out32)[warp * 32 + lane] = r;
    if (out16) {
        uint2 o;
        *reinterpret_cast<__half2*>(&o.x) = __floats2half2_rn(di * r.x, di * r.y);
        *reinterpret_cast<__half2*>(&o.y) = __floats2half2_rn(di * r.z, di * r.w);
        reinterpret_cast<uint2*>(out16)[warp * 32 + lane] = o;
    }
}

// ---------------- mean pool over sorted batch ---------------------------------
__global__ __launch_bounds__(128) void pool_kernel(const int* __restrict__ batch,
                                                   const float* __restrict__ h)
{
    int g = blockIdx.x;
    __shared__ int s_beg, s_end;
    if (threadIdx.x == 0) {
        int lo = 0, hi = N_NODES;
        while (lo < hi) { int m = (lo + hi) >> 1; if (batch[m] < g) lo = m + 1; else hi = m; }
        s_beg = lo;
        lo = 0; hi = N_NODES;
        while (lo < hi) { int m = (lo + hi) >> 1; if (batch[m] < g + 1) lo = m + 1; else hi = m; }
        s_end = lo;
    }
    __syncthreads();
    int f = threadIdx.x;
    float sum = 0.f;
    for (int n = s_beg; n < s_end; n++) sum += h[n * 128 + f];
    float cnt = (float)(s_end - s_beg);
    g_s[g * 128 + f] = sum / fmaxf(cnt, 1.0f);
}

// ---------------- out[g,c] = s[g,:] @ WC[:,c] + bc[c] -------------------------
__global__ void out_kernel(float* __restrict__ out) {
    int t = blockIdx.x * blockDim.x + threadIdx.x;
    if (t < N_GRAPHS * N_CLASSES) {
        int g = t / N_CLASSES, c = t % N_CLASSES;
        float s = g_bc[c];
        for (int k = 0; k < HIDDEN; k++) s = fmaf(g_s[g * 128 + k], g_WC[k * N_CLASSES + c], s);
        out[t] = s;
    }
}

// ---------------- launcher ----------------------------------------------------
extern "C" void kernel_launch(void* const* d_in, const int* in_sizes, int n_in,
                              void* d_out, int out_size)
{
    const float* x     = (const float*)d_in[0];
    const int*   ei    = (const int*)  d_in[1];
    const int*   batch = (const int*)  d_in[2];
    const float* W1    = (const float*)d_in[3];
    const float* b1    = (const float*)d_in[4];
    const float* W2    = (const float*)d_in[5];
    const float* b2    = (const float*)d_in[6];
    const float* W3    = (const float*)d_in[7];
    const float* b3    = (const float*)d_in[8];
    const float* Wl    = (const float*)d_in[9];
    const float* bl    = (const float*)d_in[10];
    float* out = (float*)d_out;

    float *hb, *zb;
    __half *y16, *h16;
    void* wfragPtr;
    cudaGetSymbolAddress((void**)&hb, g_h);
    cudaGetSymbolAddress((void**)&zb, g_z);
    cudaGetSymbolAddress((void**)&y16, g_y16);
    cudaGetSymbolAddress((void**)&h16, g_h16);
    cudaGetSymbolAddress(&wfragPtr, g_wfrag);
    const float4* wf1 = (const float4*)wfragPtr;
    const float4* wf2 = wf1 + 8192;

    const int AGG_BLOCKS = (N_NODES + 7) / 8;

    // prep (wfrag + deg=0 + head fold), GEMM1 || count, scan, fill || y1-rescale
    prep_kernel<<<107, 256>>>(W1, W2, W3, b3, Wl, bl);
    gemm1_count_kernel<<<GEMM_BLOCKS + CNT_BLOCKS, 256>>>(x, wf1, y16, ei);
    scan_kernel<<<1, 1024>>>();
    fill_scale_kernel<<<FILL_BLOCKS + SCALE_BLOCKS, 256>>>(ei, y16);

    // layer 1: gather y1' -> h1 fp32
    agg_kernel<<<AGG_BLOCKS, 256>>>(y16, hb, (__half*)nullptr, b1, 1);
    // layer 2: gemm h1 -> y2' (dinv-scaled fp16); gather -> h2' fp16 (pre-scaled)
    gemm_tf32_kernel<<<GEMM_BLOCKS, 256>>>(hb, wf2, y16);
    agg_kernel<<<AGG_BLOCKS, 256>>>(y16, (float*)nullptr, h16, b2, 1);
    // layer 3 (reassociated): gather h2' -> z3 fp32
    agg_kernel<<<AGG_BLOCKS, 256>>>(h16, zb, (__half*)nullptr, (const float*)nullptr, 0);

    // pool + folded head
    pool_kernel<<<N_GRAPHS, 128>>>(batch, zb);
    out_kernel<<<(N_GRAPHS * N_CLASSES + 255) / 256, 256>>>(out);
}

// round 11
// speedup vs baseline: 1.3294x; 1.0364x over previous
#include <cuda_runtime.h>
#include <cuda_bf16.h>
#include <cuda_fp16.h>
#include <cstdint>

#define N_NODES 40000
#define N_EDGES 640000
#define HIDDEN  128
#define N_GRAPHS 256
#define N_CLASSES 5

#define GEMM_BLOCKS 313          // ceil(40000/128)
#define CNT_BLOCKS  625          // 640000/4/256
#define FILL_BLOCKS 1250         // 640000/2/256
#define CSR_CAP     (N_EDGES + 3 * N_NODES)   // padded CSR capacity (760000)
#define PREF_BLOCKS 743          // ceil(CSR_CAP/4/256)  sentinel prefill

// ---------------- scratch (static device globals; no runtime alloc) ----------
// NOTE: g_deg is zero at every launch entry: zero-initialized statically, and
// scan_kernel re-zeroes it after consuming (deterministic across graph replays).
__device__ __align__(16) float  g_h[N_NODES * HIDDEN];          // h1 fp32 (gemm2 input)
__device__ __align__(16) float  g_z[N_NODES * HIDDEN];          // z3 fp32 (pool input)
__device__ __align__(16) __half g_y16[(N_NODES + 1) * HIDDEN];  // gather src (+ zero row)
__device__ __align__(16) __half g_h16[(N_NODES + 1) * HIDDEN];  // gather src (+ zero row)
__device__ __align__(16) float  g_dinv[N_NODES];
__device__ __align__(16) int    g_deg[N_NODES];
__device__ __align__(16) int    g_rowptr[N_NODES + 4];
__device__ __align__(16) int    g_cursor[N_NODES];
__device__ __align__(16) int    g_csrc[CSR_CAP + 16];
__device__ float g_s[N_GRAPHS * HIDDEN];    // pooled means
__device__ float g_WC[HIDDEN * N_CLASSES];  // W3 @ Wl
__device__ float g_bc[N_CLASSES];           // b3 @ Wl + bl
// Precomputed W fragments for tf32 MMA, per layer:
// [ (ks*16 + nt)*32 + lane ] -> float4 { b0_hi, b1_hi, b0_lo, b1_lo }
__device__ __align__(16) float g_wfrag[2][16 * 16 * 32 * 4];

// ---------------- helpers -----------------------------------------------------
__device__ __forceinline__ unsigned f2tf32(float f) {
    unsigned u;
    asm("cvt.rna.tf32.f32 %0, %1;" : "=r"(u) : "f"(f));
    return u;
}

__device__ __forceinline__ void mma_tf32(float* d,
                                         unsigned a0, unsigned a1, unsigned a2, unsigned a3,
                                         unsigned b0, unsigned b1)
{
    asm volatile(
        "mma.sync.aligned.m16n8k8.row.col.f32.tf32.tf32.f32 "
        "{%0,%1,%2,%3}, {%4,%5,%6,%7}, {%8,%9}, {%0,%1,%2,%3};"
        : "+f"(d[0]), "+f"(d[1]), "+f"(d[2]), "+f"(d[3])
        : "r"(a0), "r"(a1), "r"(a2), "r"(a3), "r"(b0), "r"(b1));
}

__device__ __forceinline__ float2 h2f2(unsigned u) {
    __half2 h = *reinterpret_cast<__half2*>(&u);
    return __half22float2(h);
}

// ---------------- GEMM body (tf32 split precision) -> fp16 output -------------
// Y16 = half( (scale ? dinv[row] : 1) * (A @ W) )
__device__ __forceinline__ void gemm_body(int bid, const float* __restrict__ A,
                                          const float4* __restrict__ wfrag,
                                          __half* __restrict__ Y16, int scale)
{
    __shared__ __align__(16) float s_a[128 * 68];   // 128 rows x 64 k-cols, pad 4

    int tid  = threadIdx.x;
    int warp = tid >> 5;
    int lane = tid & 31;
    int row0 = bid * 128;
    int wrow = row0 + warp * 16;

    float acc[64];
    #pragma unroll
    for (int i = 0; i < 64; i++) acc[i] = 0.f;

    const uint4* bf = reinterpret_cast<const uint4*>(wfrag);

    #pragma unroll
    for (int kh = 0; kh < 2; kh++) {
        #pragma unroll
        for (int j = 0; j < 8; j++) {
            int idx = tid + 256 * j;            // 0..2047
            int r = idx >> 4;                   // 0..127
            int c = (idx & 15) * 4;             // 0..60
            int gr = row0 + r;
            float4 v = make_float4(0.f, 0.f, 0.f, 0.f);
            if (gr < N_NODES)
                v = *reinterpret_cast<const float4*>(&A[gr * 128 + kh * 64 + c]);
            *reinterpret_cast<float4*>(&s_a[r * 68 + c]) = v;
        }
        __syncthreads();

        #pragma unroll
        for (int ksl = 0; ksl < 8; ksl++) {
            int ks = kh * 8 + ksl;
            int c  = ksl * 8 + (lane & 3);
            int rA = warp * 16 + (lane >> 2);
            float f0 = s_a[rA * 68 + c];
            float f1 = s_a[(rA + 8) * 68 + c];
            float f2 = s_a[rA * 68 + c + 4];
            float f3 = s_a[(rA + 8) * 68 + c + 4];
            unsigned ah0 = f2tf32(f0), ah1 = f2tf32(f1), ah2 = f2tf32(f2), ah3 = f2tf32(f3);
            unsigned al0 = f2tf32(f0 - __uint_as_float(ah0));
            unsigned al1 = f2tf32(f1 - __uint_as_float(ah1));
            unsigned al2 = f2tf32(f2 - __uint_as_float(ah2));
            unsigned al3 = f2tf32(f3 - __uint_as_float(ah3));

            const uint4* bk = bf + ks * (16 * 32) + lane;
            #pragma unroll
            for (int nt = 0; nt < 16; nt++) {
                uint4 b = __ldg(bk + nt * 32);   // {b0_hi, b1_hi, b0_lo, b1_lo}
                float* d = acc + nt * 4;
                mma_tf32(d, ah0, ah1, ah2, ah3, b.x, b.y);  // hi*hi
                mma_tf32(d, ah0, ah1, ah2, ah3, b.z, b.w);  // hi*lo
                mma_tf32(d, al0, al1, al2, al3, b.x, b.y);  // lo*hi
            }
        }
        __syncthreads();
    }

    if (wrow < N_NODES) {
        int r0 = wrow + (lane >> 2);
        int r1 = r0 + 8;
        float d0 = scale ? g_dinv[r0] : 1.f;
        float d1 = scale ? g_dinv[r1] : 1.f;
        #pragma unroll
        for (int nt = 0; nt < 16; nt++) {
            int col = nt * 8 + (lane & 3) * 2;
            __half2 p0 = __floats2half2_rn(d0 * acc[nt * 4 + 0], d0 * acc[nt * 4 + 1]);
            __half2 p1 = __floats2half2_rn(d1 * acc[nt * 4 + 2], d1 * acc[nt * 4 + 3]);
            *reinterpret_cast<__half2*>(&Y16[r0 * 128 + col]) = p0;
            *reinterpret_cast<__half2*>(&Y16[r1 * 128 + col]) = p1;
        }
    }
}

// ---------------- prep: wfrag + csrc sentinel prefill + deg count + head ------
// blocks [0,64): wfrag
// [64, 64+PREF_BLOCKS): fill g_csrc with sentinel N_NODES
// [64+PREF_BLOCKS, +CNT_BLOCKS): degree count (deg is zero at entry; see note)
// [next, +3): head fold; [last]: zero sentinel rows of g_y16/g_h16
__global__ __launch_bounds__(256) void prep_kernel(
    const float* __restrict__ W1, const float* __restrict__ W2,
    const float* __restrict__ W3, const float* __restrict__ b3,
    const float* __restrict__ Wl, const float* __restrict__ bl,
    const int* __restrict__ ei)
{
    const int B_PREF = 64;
    const int B_CNT  = B_PREF + PREF_BLOCKS;
    const int B_HEAD = B_CNT + CNT_BLOCKS;
    const int B_ZROW = B_HEAD + 3;

    if (blockIdx.x < B_PREF) {
        int t = blockIdx.x * 256 + threadIdx.x;     // 0..16383
        int layer = t >> 13;
        int r = t & 8191;                 // (ks*16 + nt)*32 + lane
        int ks   = r >> 9;
        int lane = r & 31;
        int k0 = ks * 8 + (lane & 3);
        int n  = ((r >> 5) & 15) * 8 + (lane >> 2);
        const float* W = layer ? W2 : W1;
        float b0 = W[k0 * HIDDEN + n];
        float b1 = W[(k0 + 4) * HIDDEN + n];
        unsigned h0 = f2tf32(b0);
        unsigned h1 = f2tf32(b1);
        unsigned l0 = f2tf32(b0 - __uint_as_float(h0));
        unsigned l1 = f2tf32(b1 - __uint_as_float(h1));
        float4 o = make_float4(__uint_as_float(h0), __uint_as_float(h1),
                               __uint_as_float(l0), __uint_as_float(l1));
        *reinterpret_cast<float4*>(&g_wfrag[layer][r * 4]) = o;
    } else if (blockIdx.x < B_CNT) {
        int t = (blockIdx.x - B_PREF) * 256 + threadIdx.x;   // int4 index
        if (t < CSR_CAP / 4)
            *reinterpret_cast<int4*>(&g_csrc[t * 4]) =
                make_int4(N_NODES, N_NODES, N_NODES, N_NODES);
    } else if (blockIdx.x < B_HEAD) {
        int e4 = ((blockIdx.x - B_CNT) * 256 + threadIdx.x) * 4;
        if (e4 < N_EDGES) {
            int4 d = *reinterpret_cast<const int4*>(&ei[N_EDGES + e4]);
            atomicAdd(&g_deg[d.x], 1);
            atomicAdd(&g_deg[d.y], 1);
            atomicAdd(&g_deg[d.z], 1);
            atomicAdd(&g_deg[d.w], 1);
        }
    } else if (blockIdx.x < B_ZROW) {
        int t = (blockIdx.x - B_HEAD) * 256 + threadIdx.x;
        if (t < HIDDEN * N_CLASSES) {
            int j = t / N_CLASSES, c = t % N_CLASSES;
            float s = 0.f;
            for (int k = 0; k < HIDDEN; k++) s = fmaf(W3[j * HIDDEN + k], Wl[k * N_CLASSES + c], s);
            g_WC[t] = s;
        } else if (t < HIDDEN * N_CLASSES + N_CLASSES) {
            int c = t - HIDDEN * N_CLASSES;
            float s = bl[c];
            for (int k = 0; k < HIDDEN; k++) s = fmaf(b3[k], Wl[k * N_CLASSES + c], s);
            g_bc[c] = s;
        }
    } else {
        // zero the sentinel rows (row N_NODES) of both fp16 gather buffers
        int t = threadIdx.x;
        if (t < 64)
            reinterpret_cast<uint*>(&g_y16[N_NODES * HIDDEN])[t] = 0u;
        else if (t < 128)
            reinterpret_cast<uint*>(&g_h16[N_NODES * HIDDEN])[t - 64] = 0u;
    }
}

// ---------------- scan: padded rowptr/cursor/dinv; re-zeroes deg --------------
// Segments padded to multiples of 4 (padding slots hold sentinel -> zero row).
__global__ void scan_kernel() {
    const int NT = 1024;
    int tid = threadIdx.x;
    int lane = tid & 31, wid = tid >> 5;
    __shared__ int wsum[32];
    __shared__ int s_carry;
    if (tid == 0) s_carry = 0;
    __syncthreads();
    for (int base = 0; base < N_NODES; base += NT * 4) {
        int i4 = base + tid * 4;
        int4 v = make_int4(0, 0, 0, 0);
        if (i4 < N_NODES)
            v = *reinterpret_cast<const int4*>(&g_deg[i4]);
        int4 p = make_int4((v.x + 3) & ~3, (v.y + 3) & ~3,
                           (v.z + 3) & ~3, (v.w + 3) & ~3);
        int s = p.x + p.y + p.z + p.w;
        int x = s;
        #pragma unroll
        for (int d = 1; d < 32; d <<= 1) {
            int t = __shfl_up_sync(0xffffffffu, x, d);
            if (lane >= d) x += t;
        }
        if (lane == 31) wsum[wid] = x;
        __syncthreads();
        if (wid == 0) {
            int w = wsum[lane];
            #pragma unroll
            for (int d = 1; d < 32; d <<= 1) {
                int t = __shfl_up_sync(0xffffffffu, w, d);
                if (lane >= d) w += t;
            }
            wsum[lane] = w;
        }
        __syncthreads();
        int carry = s_carry;
        int woff = (wid == 0) ? 0 : wsum[wid - 1];
        int incl = x + woff + carry;
        int e0 = incl - s;
        if (i4 < N_NODES) {
            int4 rp = make_int4(e0, e0 + p.x, e0 + p.x + p.y, e0 + p.x + p.y + p.z);
            *reinterpret_cast<int4*>(&g_rowptr[i4]) = rp;
            *reinterpret_cast<int4*>(&g_cursor[i4]) = rp;
            float4 dv = make_float4(rsqrtf((float)(v.x + 1)), rsqrtf((float)(v.y + 1)),
                                    rsqrtf((float)(v.z + 1)), rsqrtf((float)(v.w + 1)));
            *reinterpret_cast<float4*>(&g_dinv[i4]) = dv;
            // restore the launch-entry invariant deg == 0 for the next call
            *reinterpret_cast<int4*>(&g_deg[i4]) = make_int4(0, 0, 0, 0);
        }
        __syncthreads();
        if (tid == NT - 1) s_carry = incl;
        __syncthreads();
    }
    if (tid == 0) g_rowptr[N_NODES] = s_carry;
}

// ---------------- fused: GEMM layer-1 (dinv epilogue) + CSR fill --------------
// blocks [0,GEMM_BLOCKS): GEMM1 (dinv ready after scan); rest: fill 2 edges/thr
__global__ __launch_bounds__(256) void gemm1_fill_kernel(
    const float* __restrict__ A, const float4* __restrict__ wfrag,
    __half* __restrict__ Y16, const int* __restrict__ ei)
{
    if (blockIdx.x < GEMM_BLOCKS) {
        gemm_body(blockIdx.x, A, wfrag, Y16, 1);
    } else {
        int e2 = ((blockIdx.x - GEMM_BLOCKS) * 256 + threadIdx.x) * 2;
        if (e2 < N_EDGES) {
            int2 s = *reinterpret_cast<const int2*>(&ei[e2]);
            int2 d = *reinterpret_cast<const int2*>(&ei[N_EDGES + e2]);
            int p0 = atomicAdd(&g_cursor[d.x], 1);
            int p1 = atomicAdd(&g_cursor[d.y], 1);
            g_csrc[p0] = s.x;
            g_csrc[p1] = s.y;
        }
    }
}

// ---------------- standalone GEMM (layer 2, epilogue applies dinv) ------------
__global__ __launch_bounds__(256) void gemm_tf32_kernel(
    const float* __restrict__ A, const float4* __restrict__ wfrag,
    __half* __restrict__ Y16)
{
    gemm_body(blockIdx.x, A, wfrag, Y16, 1);
}

// ---------------- Aggregation (padded CSR, tail-free fp16 gather-sum) ---------
// Rows pre-scaled by dinv[src]:  r = dinv[i] * (self + sum_in row[s]) + b
// Padding indices hit the zero sentinel row (harmless adds).
__global__ __launch_bounds__(256) void agg_kernel(
    const __half* __restrict__ y16,
    float* __restrict__ out32, __half* __restrict__ out16,
    const float* __restrict__ bias, int do_relu)
{
    int warp = (blockIdx.x * blockDim.x + threadIdx.x) >> 5;
    int lane = threadIdx.x & 31;
    if (warp >= N_NODES) return;

    const uint2* y8 = reinterpret_cast<const uint2*>(y16);   // 4 halves per lane
    float di = g_dinv[warp];

    uint2 sv = y8[warp * 32 + lane];
    float2 sa = h2f2(sv.x), sb = h2f2(sv.y);
    float4 acc0 = make_float4(sa.x, sa.y, sb.x, sb.y);
    float4 acc1 = make_float4(0.f, 0.f, 0.f, 0.f);

    int e   = g_rowptr[warp];
    int end = g_rowptr[warp + 1];

    for (; e < end; e += 4) {
        int4 idx = *reinterpret_cast<const int4*>(&g_csrc[e]);  // aligned, broadcast
        uint2 v0 = __ldg(&y8[idx.x * 32 + lane]);
        uint2 v1 = __ldg(&y8[idx.y * 32 + lane]);
        uint2 v2 = __ldg(&y8[idx.z * 32 + lane]);
        uint2 v3 = __ldg(&y8[idx.w * 32 + lane]);
        float2 a0 = h2f2(v0.x), b0 = h2f2(v0.y);
        float2 a1 = h2f2(v1.x), b1 = h2f2(v1.y);
        float2 a2 = h2f2(v2.x), b2 = h2f2(v2.y);
        float2 a3 = h2f2(v3.x), b3 = h2f2(v3.y);
        acc0.x += a0.x; acc0.y += a0.y; acc0.z += b0.x; acc0.w += b0.y;
        acc1.x += a1.x; acc1.y += a1.y; acc1.z += b1.x; acc1.w += b1.y;
        acc0.x += a2.x; acc0.y += a2.y; acc0.z += b2.x; acc0.w += b2.y;
        acc1.x += a3.x; acc1.y += a3.y; acc1.z += b3.x; acc1.w += b3.y;
    }

    acc0.x += acc1.x; acc0.y += acc1.y; acc0.z += acc1.z; acc0.w += acc1.w;

    float4 b = bias ? reinterpret_cast<const float4*>(bias)[lane]
                    : make_float4(0.f, 0.f, 0.f, 0.f);
    float4 r;
    r.x = fmaf(di, acc0.x, b.x);
    r.y = fmaf(di, acc0.y, b.y);
    r.z = fmaf(di, acc0.z, b.z);
    r.w = fmaf(di, acc0.w, b.w);
    if (do_relu) {
        r.x = fmaxf(r.x, 0.f); r.y = fmaxf(r.y, 0.f);
        r.z = fmaxf(r.z, 0.f); r.w = fmaxf(r.w, 0.f);
    }
    if (out32)
        reinterpret_cast<float4*>(out32)[warp * 32 + lane] = r;
    if (out16) {
        uint2 o;
        *reinterpret_cast<__half2*>(&o.x) = __floats2half2_rn(di * r.x, di * r.y);
        *reinterpret_cast<__half2*>(&o.y) = __floats2half2_rn(di * r.z, di * r.w);
        reinterpret_cast<uint2*>(out16)[warp * 32 + lane] = o;
    }
}

// ---------------- mean pool over sorted batch ---------------------------------
__global__ __launch_bounds__(128) void pool_kernel(const int* __restrict__ batch,
                                                   const float* __restrict__ h)
{
    int g = blockIdx.x;
    __shared__ int s_beg, s_end;
    if (threadIdx.x == 0) {
        int lo = 0, hi = N_NODES;
        while (lo < hi) { int m = (lo + hi) >> 1; if (batch[m] < g) lo = m + 1; else hi = m; }
        s_beg = lo;
        lo = 0; hi = N_NODES;
        while (lo < hi) { int m = (lo + hi) >> 1; if (batch[m] < g + 1) lo = m + 1; else hi = m; }
        s_end = lo;
    }
    __syncthreads();
    int f = threadIdx.x;
    float sum = 0.f;
    for (int n = s_beg; n < s_end; n++) sum += h[n * 128 + f];
    float cnt = (float)(s_end - s_beg);
    g_s[g * 128 + f] = sum / fmaxf(cnt, 1.0f);
}

// ---------------- out[g,c] = s[g,:] @ WC[:,c] + bc[c] -------------------------
__global__ void out_kernel(float* __restrict__ out) {
    int t = blockIdx.x * blockDim.x + threadIdx.x;
    if (t < N_GRAPHS * N_CLASSES) {
        int g = t / N_CLASSES, c = t % N_CLASSES;
        float s = g_bc[c];
        for (int k = 0; k < HIDDEN; k++) s = fmaf(g_s[g * 128 + k], g_WC[k * N_CLASSES + c], s);
        out[t] = s;
    }
}

// ---------------- launcher ----------------------------------------------------
extern "C" void kernel_launch(void* const* d_in, const int* in_sizes, int n_in,
                              void* d_out, int out_size)
{
    const float* x     = (const float*)d_in[0];
    const int*   ei    = (const int*)  d_in[1];
    const int*   batch = (const int*)  d_in[2];
    const float* W1    = (const float*)d_in[3];
    const float* b1    = (const float*)d_in[4];
    const float* W2    = (const float*)d_in[5];
    const float* b2    = (const float*)d_in[6];
    const float* W3    = (const float*)d_in[7];
    const float* b3    = (const float*)d_in[8];
    const float* Wl    = (const float*)d_in[9];
    const float* bl    = (const float*)d_in[10];
    float* out = (float*)d_out;

    float *hb, *zb;
    __half *y16, *h16;
    void* wfragPtr;
    cudaGetSymbolAddress((void**)&hb, g_h);
    cudaGetSymbolAddress((void**)&zb, g_z);
    cudaGetSymbolAddress((void**)&y16, g_y16);
    cudaGetSymbolAddress((void**)&h16, g_h16);
    cudaGetSymbolAddress(&wfragPtr, g_wfrag);
    const float4* wf1 = (const float4*)wfragPtr;
    const float4* wf2 = wf1 + 8192;

    const int AGG_BLOCKS = (N_NODES + 7) / 8;
    const int PREP_GRID  = 64 + PREF_BLOCKS + CNT_BLOCKS + 3 + 1;

    // prep (wfrag + csrc sentinel + deg count + head + zero rows)
    prep_kernel<<<PREP_GRID, 256>>>(W1, W2, W3, b3, Wl, bl, ei);
    // scan (padded rowptr; re-zeroes deg)
    scan_kernel<<<1, 1024>>>();
    // GEMM1 (dinv epilogue) || CSR fill
    gemm1_fill_kernel<<<GEMM_BLOCKS + FILL_BLOCKS, 256>>>(x, wf1, y16, ei);

    // layer 1: gather y1' -> h1 fp32
    agg_kernel<<<AGG_BLOCKS, 256>>>(y16, hb, (__half*)nullptr, b1, 1);
    // layer 2: gemm h1 -> y2' (dinv-scaled fp16); gather -> h2' fp16 (pre-scaled)
    gemm_tf32_kernel<<<GEMM_BLOCKS, 256>>>(hb, wf2, y16);
    agg_kernel<<<AGG_BLOCKS, 256>>>(y16, (float*)nullptr, h16, b2, 1);
    // layer 3 (reassociated): gather h2' -> z3 fp32
    agg_kernel<<<AGG_BLOCKS, 256>>>(h16, zb, (__half*)nullptr, (const float*)nullptr, 0);

    // pool + folded head
    pool_kernel<<<N_GRAPHS, 128>>>(batch, zb);
    out_kernel<<<(N_GRAPHS * N_CLASSES + 255) / 256, 256>>>(out);
}

// round 12
// speedup vs baseline: 1.3993x; 1.0526x over previous
#include <cuda_runtime.h>
#include <cuda_bf16.h>
#include <cuda_fp16.h>
#include <cstdint>

#define N_NODES 40000
#define N_EDGES 640000
#define HIDDEN  128
#define N_GRAPHS 256
#define N_CLASSES 5

#define GEMM_BLOCKS 313          // ceil(40000/128)
#define CNT_BLOCKS  625          // 640000/4/256
#define FILL_BLOCKS 1250         // 640000/2/256
#define CSR_CAP     (N_EDGES + 7 * N_NODES)   // segments padded to mult of 8 (920000)
#define PREF_BLOCKS 899          // ceil(CSR_CAP/4/256)  sentinel prefill

// ---------------- scratch (static device globals; no runtime alloc) ----------
// NOTE: g_deg is zero at every launch entry: zero-initialized statically, and
// scan_kernel re-zeroes it after consuming (deterministic across graph replays).
__device__ __align__(16) float  g_h[N_NODES * HIDDEN];          // h1 fp32 (gemm2 input)
__device__ __align__(16) float  g_z[N_NODES * HIDDEN];          // z3 fp32 (pool input)
__device__ __align__(16) __half g_y16[(N_NODES + 1) * HIDDEN];  // gather src (+ zero row)
__device__ __align__(16) __half g_h16[(N_NODES + 1) * HIDDEN];  // gather src (+ zero row)
__device__ __align__(16) float  g_dinv[N_NODES];
__device__ __align__(16) int    g_deg[N_NODES];
__device__ __align__(16) int    g_rowptr[N_NODES + 4];
__device__ __align__(16) int    g_cursor[N_NODES];
__device__ __align__(16) int    g_csrc[CSR_CAP + 16];
__device__ float g_s[N_GRAPHS * HIDDEN];    // pooled means
__device__ float g_WC[HIDDEN * N_CLASSES];  // W3 @ Wl
__device__ float g_bc[N_CLASSES];           // b3 @ Wl + bl
// Precomputed W fragments for tf32 MMA, per layer:
// [ (ks*16 + nt)*32 + lane ] -> float4 { b0_hi, b1_hi, b0_lo, b1_lo }
__device__ __align__(16) float g_wfrag[2][16 * 16 * 32 * 4];

// ---------------- helpers -----------------------------------------------------
__device__ __forceinline__ unsigned f2tf32(float f) {
    unsigned u;
    asm("cvt.rna.tf32.f32 %0, %1;" : "=r"(u) : "f"(f));
    return u;
}

__device__ __forceinline__ void mma_tf32(float* d,
                                         unsigned a0, unsigned a1, unsigned a2, unsigned a3,
                                         unsigned b0, unsigned b1)
{
    asm volatile(
        "mma.sync.aligned.m16n8k8.row.col.f32.tf32.tf32.f32 "
        "{%0,%1,%2,%3}, {%4,%5,%6,%7}, {%8,%9}, {%0,%1,%2,%3};"
        : "+f"(d[0]), "+f"(d[1]), "+f"(d[2]), "+f"(d[3])
        : "r"(a0), "r"(a1), "r"(a2), "r"(a3), "r"(b0), "r"(b1));
}

__device__ __forceinline__ float2 h2f2(unsigned u) {
    __half2 h = *reinterpret_cast<__half2*>(&u);
    return __half22float2(h);
}

__device__ __forceinline__ __half2 u2h(unsigned u) {
    return *reinterpret_cast<__half2*>(&u);
}

// ---------------- GEMM body (tf32 split precision) -> fp16 output -------------
// Y16 = half( (scale ? dinv[row] : 1) * (A @ W) )
__device__ __forceinline__ void gemm_body(int bid, const float* __restrict__ A,
                                          const float4* __restrict__ wfrag,
                                          __half* __restrict__ Y16, int scale)
{
    __shared__ __align__(16) float s_a[128 * 68];   // 128 rows x 64 k-cols, pad 4

    int tid  = threadIdx.x;
    int warp = tid >> 5;
    int lane = tid & 31;
    int row0 = bid * 128;
    int wrow = row0 + warp * 16;

    float acc[64];
    #pragma unroll
    for (int i = 0; i < 64; i++) acc[i] = 0.f;

    const uint4* bf = reinterpret_cast<const uint4*>(wfrag);

    #pragma unroll
    for (int kh = 0; kh < 2; kh++) {
        #pragma unroll
        for (int j = 0; j < 8; j++) {
            int idx = tid + 256 * j;            // 0..2047
            int r = idx >> 4;                   // 0..127
            int c = (idx & 15) * 4;             // 0..60
            int gr = row0 + r;
            float4 v = make_float4(0.f, 0.f, 0.f, 0.f);
            if (gr < N_NODES)
                v = *reinterpret_cast<const float4*>(&A[gr * 128 + kh * 64 + c]);
            *reinterpret_cast<float4*>(&s_a[r * 68 + c]) = v;
        }
        __syncthreads();

        #pragma unroll
        for (int ksl = 0; ksl < 8; ksl++) {
            int ks = kh * 8 + ksl;
            int c  = ksl * 8 + (lane & 3);
            int rA = warp * 16 + (lane >> 2);
            float f0 = s_a[rA * 68 + c];
            float f1 = s_a[(rA + 8) * 68 + c];
            float f2 = s_a[rA * 68 + c + 4];
            float f3 = s_a[(rA + 8) * 68 + c + 4];
            unsigned ah0 = f2tf32(f0), ah1 = f2tf32(f1), ah2 = f2tf32(f2), ah3 = f2tf32(f3);
            unsigned al0 = f2tf32(f0 - __uint_as_float(ah0));
            unsigned al1 = f2tf32(f1 - __uint_as_float(ah1));
            unsigned al2 = f2tf32(f2 - __uint_as_float(ah2));
            unsigned al3 = f2tf32(f3 - __uint_as_float(ah3));

            const uint4* bk = bf + ks * (16 * 32) + lane;
            #pragma unroll
            for (int nt = 0; nt < 16; nt++) {
                uint4 b = __ldg(bk + nt * 32);   // {b0_hi, b1_hi, b0_lo, b1_lo}
                float* d = acc + nt * 4;
                mma_tf32(d, ah0, ah1, ah2, ah3, b.x, b.y);  // hi*hi
                mma_tf32(d, ah0, ah1, ah2, ah3, b.z, b.w);  // hi*lo
                mma_tf32(d, al0, al1, al2, al3, b.x, b.y);  // lo*hi
            }
        }
        __syncthreads();
    }

    if (wrow < N_NODES) {
        int r0 = wrow + (lane >> 2);
        int r1 = r0 + 8;
        float d0 = scale ? g_dinv[r0] : 1.f;
        float d1 = scale ? g_dinv[r1] : 1.f;
        #pragma unroll
        for (int nt = 0; nt < 16; nt++) {
            int col = nt * 8 + (lane & 3) * 2;
            __half2 p0 = __floats2half2_rn(d0 * acc[nt * 4 + 0], d0 * acc[nt * 4 + 1]);
            __half2 p1 = __floats2half2_rn(d1 * acc[nt * 4 + 2], d1 * acc[nt * 4 + 3]);
            *reinterpret_cast<__half2*>(&Y16[r0 * 128 + col]) = p0;
            *reinterpret_cast<__half2*>(&Y16[r1 * 128 + col]) = p1;
        }
    }
}

// ---------------- prep: wfrag + csrc sentinel prefill + deg count + head ------
__global__ __launch_bounds__(256) void prep_kernel(
    const float* __restrict__ W1, const float* __restrict__ W2,
    const float* __restrict__ W3, const float* __restrict__ b3,
    const float* __restrict__ Wl, const float* __restrict__ bl,
    const int* __restrict__ ei)
{
    const int B_PREF = 64;
    const int B_CNT  = B_PREF + PREF_BLOCKS;
    const int B_HEAD = B_CNT + CNT_BLOCKS;
    const int B_ZROW = B_HEAD + 3;

    if (blockIdx.x < B_PREF) {
        int t = blockIdx.x * 256 + threadIdx.x;     // 0..16383
        int layer = t >> 13;
        int r = t & 8191;                 // (ks*16 + nt)*32 + lane
        int ks   = r >> 9;
        int lane = r & 31;
        int k0 = ks * 8 + (lane & 3);
        int n  = ((r >> 5) & 15) * 8 + (lane >> 2);
        const float* W = layer ? W2 : W1;
        float b0 = W[k0 * HIDDEN + n];
        float b1 = W[(k0 + 4) * HIDDEN + n];
        unsigned h0 = f2tf32(b0);
        unsigned h1 = f2tf32(b1);
        unsigned l0 = f2tf32(b0 - __uint_as_float(h0));
        unsigned l1 = f2tf32(b1 - __uint_as_float(h1));
        float4 o = make_float4(__uint_as_float(h0), __uint_as_float(h1),
                               __uint_as_float(l0), __uint_as_float(l1));
        *reinterpret_cast<float4*>(&g_wfrag[layer][r * 4]) = o;
    } else if (blockIdx.x < B_CNT) {
        int t = (blockIdx.x - B_PREF) * 256 + threadIdx.x;   // int4 index
        if (t < CSR_CAP / 4)
            *reinterpret_cast<int4*>(&g_csrc[t * 4]) =
                make_int4(N_NODES, N_NODES, N_NODES, N_NODES);
    } else if (blockIdx.x < B_HEAD) {
        int e4 = ((blockIdx.x - B_CNT) * 256 + threadIdx.x) * 4;
        if (e4 < N_EDGES) {
            int4 d = *reinterpret_cast<const int4*>(&ei[N_EDGES + e4]);
            atomicAdd(&g_deg[d.x], 1);
            atomicAdd(&g_deg[d.y], 1);
            atomicAdd(&g_deg[d.z], 1);
            atomicAdd(&g_deg[d.w], 1);
        }
    } else if (blockIdx.x < B_ZROW) {
        int t = (blockIdx.x - B_HEAD) * 256 + threadIdx.x;
        if (t < HIDDEN * N_CLASSES) {
            int j = t / N_CLASSES, c = t % N_CLASSES;
            float s = 0.f;
            for (int k = 0; k < HIDDEN; k++) s = fmaf(W3[j * HIDDEN + k], Wl[k * N_CLASSES + c], s);
            g_WC[t] = s;
        } else if (t < HIDDEN * N_CLASSES + N_CLASSES) {
            int c = t - HIDDEN * N_CLASSES;
            float s = bl[c];
            for (int k = 0; k < HIDDEN; k++) s = fmaf(b3[k], Wl[k * N_CLASSES + c], s);
            g_bc[c] = s;
        }
    } else {
        // zero the sentinel rows (row N_NODES) of both fp16 gather buffers
        int t = threadIdx.x;
        if (t < 64)
            reinterpret_cast<uint*>(&g_y16[N_NODES * HIDDEN])[t] = 0u;
        else if (t < 128)
            reinterpret_cast<uint*>(&g_h16[N_NODES * HIDDEN])[t - 64] = 0u;
    }
}

// ---------------- scan: rowptr padded to mult-of-8; re-zeroes deg -------------
__global__ void scan_kernel() {
    const int NT = 1024;
    int tid = threadIdx.x;
    int lane = tid & 31, wid = tid >> 5;
    __shared__ int wsum[32];
    __shared__ int s_carry;
    if (tid == 0) s_carry = 0;
    __syncthreads();
    for (int base = 0; base < N_NODES; base += NT * 4) {
        int i4 = base + tid * 4;
        int4 v = make_int4(0, 0, 0, 0);
        if (i4 < N_NODES)
            v = *reinterpret_cast<const int4*>(&g_deg[i4]);
        int4 p = make_int4((v.x + 7) & ~7, (v.y + 7) & ~7,
                           (v.z + 7) & ~7, (v.w + 7) & ~7);
        int s = p.x + p.y + p.z + p.w;
        int x = s;
        #pragma unroll
        for (int d = 1; d < 32; d <<= 1) {
            int t = __shfl_up_sync(0xffffffffu, x, d);
            if (lane >= d) x += t;
        }
        if (lane == 31) wsum[wid] = x;
        __syncthreads();
        if (wid == 0) {
            int w = wsum[lane];
            #pragma unroll
            for (int d = 1; d < 32; d <<= 1) {
                int t = __shfl_up_sync(0xffffffffu, w, d);
                if (lane >= d) w += t;
            }
            wsum[lane] = w;
        }
        __syncthreads();
        int carry = s_carry;
        int woff = (wid == 0) ? 0 : wsum[wid - 1];
        int incl = x + woff + carry;
        int e0 = incl - s;
        if (i4 < N_NODES) {
            int4 rp = make_int4(e0, e0 + p.x, e0 + p.x + p.y, e0 + p.x + p.y + p.z);
            *reinterpret_cast<int4*>(&g_rowptr[i4]) = rp;
            *reinterpret_cast<int4*>(&g_cursor[i4]) = rp;
            float4 dv = make_float4(rsqrtf((float)(v.x + 1)), rsqrtf((float)(v.y + 1)),
                                    rsqrtf((float)(v.z + 1)), rsqrtf((float)(v.w + 1)));
            *reinterpret_cast<float4*>(&g_dinv[i4]) = dv;
            // restore the launch-entry invariant deg == 0 for the next call
            *reinterpret_cast<int4*>(&g_deg[i4]) = make_int4(0, 0, 0, 0);
        }
        __syncthreads();
        if (tid == NT - 1) s_carry = incl;
        __syncthreads();
    }
    if (tid == 0) g_rowptr[N_NODES] = s_carry;
}

// ---------------- fused: GEMM layer-1 (dinv epilogue) + CSR fill --------------
__global__ __launch_bounds__(256) void gemm1_fill_kernel(
    const float* __restrict__ A, const float4* __restrict__ wfrag,
    __half* __restrict__ Y16, const int* __restrict__ ei)
{
    if (blockIdx.x < GEMM_BLOCKS) {
        gemm_body(blockIdx.x, A, wfrag, Y16, 1);
    } else {
        int e2 = ((blockIdx.x - GEMM_BLOCKS) * 256 + threadIdx.x) * 2;
        if (e2 < N_EDGES) {
            int2 s = *reinterpret_cast<const int2*>(&ei[e2]);
            int2 d = *reinterpret_cast<const int2*>(&ei[N_EDGES + e2]);
            int p0 = atomicAdd(&g_cursor[d.x], 1);
            int p1 = atomicAdd(&g_cursor[d.y], 1);
            g_csrc[p0] = s.x;
            g_csrc[p1] = s.y;
        }
    }
}

// ---------------- standalone GEMM (layer 2, epilogue applies dinv) ------------
__global__ __launch_bounds__(256) void gemm_tf32_kernel(
    const float* __restrict__ A, const float4* __restrict__ wfrag,
    __half* __restrict__ Y16)
{
    gemm_body(blockIdx.x, A, wfrag, Y16, 1);
}

// ---------------- Aggregation: 8-edge pairwise fp16 tree, fp32 accumulate -----
// Rows pre-scaled by dinv[src]:  r = dinv[i] * (self + sum_in row[s]) + b
// Segments padded to mult of 8; padding hits the zero sentinel row.
__global__ __launch_bounds__(256) void agg_kernel(
    const __half* __restrict__ y16,
    float* __restrict__ out32, __half* __restrict__ out16,
    const float* __restrict__ bias, int do_relu)
{
    int warp = (blockIdx.x * blockDim.x + threadIdx.x) >> 5;
    int lane = threadIdx.x & 31;
    if (warp >= N_NODES) return;

    const uint2* y8 = reinterpret_cast<const uint2*>(y16);   // 4 halves per lane
    float di = g_dinv[warp];

    uint2 sv = y8[warp * 32 + lane];
    float2 sa = h2f2(sv.x), sb = h2f2(sv.y);
    float4 acc = make_float4(sa.x, sa.y, sb.x, sb.y);

    int e   = g_rowptr[warp];
    int end = g_rowptr[warp + 1];

    for (; e < end; e += 8) {
        int4 i0 = *reinterpret_cast<const int4*>(&g_csrc[e]);
        int4 i1 = *reinterpret_cast<const int4*>(&g_csrc[e + 4]);
        uint2 v0 = __ldg(&y8[i0.x * 32 + lane]);
        uint2 v1 = __ldg(&y8[i0.y * 32 + lane]);
        uint2 v2 = __ldg(&y8[i0.z * 32 + lane]);
        uint2 v3 = __ldg(&y8[i0.w * 32 + lane]);
        uint2 v4 = __ldg(&y8[i1.x * 32 + lane]);
        uint2 v5 = __ldg(&y8[i1.y * 32 + lane]);
        uint2 v6 = __ldg(&y8[i1.z * 32 + lane]);
        uint2 v7 = __ldg(&y8[i1.w * 32 + lane]);
        // pairwise fp16 trees (features 0-1 in .x, 2-3 in .y)
        __half2 x01 = __hadd2(u2h(v0.x), u2h(v1.x));
        __half2 x23 = __hadd2(u2h(v2.x), u2h(v3.x));
        __half2 x45 = __hadd2(u2h(v4.x), u2h(v5.x));
        __half2 x67 = __hadd2(u2h(v6.x), u2h(v7.x));
        __half2 xs  = __hadd2(__hadd2(x01, x23), __hadd2(x45, x67));
        __half2 y01 = __hadd2(u2h(v0.y), u2h(v1.y));
        __half2 y23 = __hadd2(u2h(v2.y), u2h(v3.y));
        __half2 y45 = __hadd2(u2h(v4.y), u2h(v5.y));
        __half2 y67 = __hadd2(u2h(v6.y), u2h(v7.y));
        __half2 ys  = __hadd2(__hadd2(y01, y23), __hadd2(y45, y67));
        float2 fx = __half22float2(xs);
        float2 fy = __half22float2(ys);
        acc.x += fx.x; acc.y += fx.y; acc.z += fy.x; acc.w += fy.y;
    }

    float4 b = bias ? reinterpret_cast<const float4*>(bias)[lane]
                    : make_float4(0.f, 0.f, 0.f, 0.f);
    float4 r;
    r.x = fmaf(di, acc.x, b.x);
    r.y = fmaf(di, acc.y, b.y);
    r.z = fmaf(di, acc.z, b.z);
    r.w = fmaf(di, acc.w, b.w);
    if (do_relu) {
        r.x = fmaxf(r.x, 0.f); r.y = fmaxf(r.y, 0.f);
        r.z = fmaxf(r.z, 0.f); r.w = fmaxf(r.w, 0.f);
    }
    if (out32)
        reinterpret_cast<float4*>(out32)[warp * 32 + lane] = r;
    if (out16) {
        uint2 o;
        *reinterpret_cast<__half2*>(&o.x) = __floats2half2_rn(di * r.x, di * r.y);
        *reinterpret_cast<__half2*>(&o.y) = __floats2half2_rn(di * r.z, di * r.w);
        reinterpret_cast<uint2*>(out16)[warp * 32 + lane] = o;
    }
}

// ---------------- mean pool over sorted batch ---------------------------------
__global__ __launch_bounds__(128) void pool_kernel(const int* __restrict__ batch,
                                                   const float* __restrict__ h)
{
    int g = blockIdx.x;
    __shared__ int s_beg, s_end;
    if (threadIdx.x == 0) {
        int lo = 0, hi = N_NODES;
        while (lo < hi) { int m = (lo + hi) >> 1; if (batch[m] < g) lo = m + 1; else hi = m; }
        s_beg = lo;
        lo = 0; hi = N_NODES;
        while (lo < hi) { int m = (lo + hi) >> 1; if (batch[m] < g + 1) lo = m + 1; else hi = m; }
        s_end = lo;
    }
    __syncthreads();
    int f = threadIdx.x;
    float sum = 0.f;
    for (int n = s_beg; n < s_end; n++) sum += h[n * 128 + f];
    float cnt = (float)(s_end - s_beg);
    g_s[g * 128 + f] = sum / fmaxf(cnt, 1.0f);
}

// ---------------- out[g,c] = s[g,:] @ WC[:,c] + bc[c] -------------------------
__global__ void out_kernel(float* __restrict__ out) {
    int t = blockIdx.x * blockDim.x + threadIdx.x;
    if (t < N_GRAPHS * N_CLASSES) {
        int g = t / N_CLASSES, c = t % N_CLASSES;
        float s = g_bc[c];
        for (int k = 0; k < HIDDEN; k++) s = fmaf(g_s[g * 128 + k], g_WC[k * N_CLASSES + c], s);
        out[t] = s;
    }
}

// ---------------- launcher ----------------------------------------------------
extern "C" void kernel_launch(void* const* d_in, const int* in_sizes, int n_in,
                              void* d_out, int out_size)
{
    const float* x     = (const float*)d_in[0];
    const int*   ei    = (const int*)  d_in[1];
    const int*   batch = (const int*)  d_in[2];
    const float* W1    = (const float*)d_in[3];
    const float* b1    = (const float*)d_in[4];
    const float* W2    = (const float*)d_in[5];
    const float* b2    = (const float*)d_in[6];
    const float* W3    = (const float*)d_in[7];
    const float* b3    = (const float*)d_in[8];
    const float* Wl    = (const float*)d_in[9];
    const float* bl    = (const float*)d_in[10];
    float* out = (float*)d_out;

    float *hb, *zb;
    __half *y16, *h16;
    void* wfragPtr;
    cudaGetSymbolAddress((void**)&hb, g_h);
    cudaGetSymbolAddress((void**)&zb, g_z);
    cudaGetSymbolAddress((void**)&y16, g_y16);
    cudaGetSymbolAddress((void**)&h16, g_h16);
    cudaGetSymbolAddress(&wfragPtr, g_wfrag);
    const float4* wf1 = (const float4*)wfragPtr;
    const float4* wf2 = wf1 + 8192;

    const int AGG_BLOCKS = (N_NODES + 7) / 8;
    const int PREP_GRID  = 64 + PREF_BLOCKS + CNT_BLOCKS + 3 + 1;

    // prep (wfrag + csrc sentinel + deg count + head + zero rows)
    prep_kernel<<<PREP_GRID, 256>>>(W1, W2, W3, b3, Wl, bl, ei);
    // scan (mult-of-8 padded rowptr; re-zeroes deg)
    scan_kernel<<<1, 1024>>>();
    // GEMM1 (dinv epilogue) || CSR fill
    gemm1_fill_kernel<<<GEMM_BLOCKS + FILL_BLOCKS, 256>>>(x, wf1, y16, ei);

    // layer 1: gather y1' -> h1 fp32
    agg_kernel<<<AGG_BLOCKS, 256>>>(y16, hb, (__half*)nullptr, b1, 1);
    // layer 2: gemm h1 -> y2' (dinv-scaled fp16); gather -> h2' fp16 (pre-scaled)
    gemm_tf32_kernel<<<GEMM_BLOCKS, 256>>>(hb, wf2, y16);
    agg_kernel<<<AGG_BLOCKS, 256>>>(y16, (float*)nullptr, h16, b2, 1);
    // layer 3 (reassociated): gather h2' -> z3 fp32
    agg_kernel<<<AGG_BLOCKS, 256>>>(h16, zb, (__half*)nullptr, (const float*)nullptr, 0);

    // pool + folded head
    pool_kernel<<<N_GRAPHS, 128>>>(batch, zb);
    out_kernel<<<(N_GRAPHS * N_CLASSES + 255) / 256, 256>>>(out);
}